// round 5
// baseline (speedup 1.0000x reference)
#include <cuda_runtime.h>
#include <math.h>

// Problem constants
#define NB   64     // batch
#define H64  64
#define W64  64
#define HWP  4096   // 64*64

// ---------------- scratch (device globals; no allocation allowed) ----------------
__device__ float g_buf1[(size_t)NB * 64 * HWP];   // conv1 out (then BN+ReLU in place)
__device__ float g_buf2[(size_t)NB * 16 * HWP];   // conv2 out (then BN+ReLU in place)
__device__ float g_offs[(size_t)NB * 18 * HWP];   // offset conv out
__device__ float g_buf3[(size_t)NB * 16 * HWP];   // deform conv out (then BN+ReLU in place)
__device__ float g_buf4[(size_t)NB * 64 * HWP];   // conv4 out (raw)
__device__ float g_stats[320];                    // per-stage sum / sumsq
__device__ float g_bnp[320];                      // per-stage scale / shift

// stats/bnp layout: [0:64]=stage1 A, [64:128]=stage1 B, [128:144]=stage2 A,
// [144:160]=stage2 B, [160:176]=stage3 A, [176:192]=stage3 B,
// [192:256]=stage4 A, [256:320]=stage4 B

// ---------------- helpers ----------------
__device__ __forceinline__ float warp_sum(float v) {
    #pragma unroll
    for (int s = 16; s > 0; s >>= 1) v += __shfl_xor_sync(0xffffffffu, v, s);
    return v;
}

__global__ void zero_stats_kernel(float* s) {
    s[threadIdx.x] = 0.0f;   // 320 threads
}

// ---------------- direct 3x3 conv, pad=1, stride=1 ----------------
// Tile: 32(x) x 32(y) outputs per block, 256 threads, each thread 2x2 pixels x COG channels.
// Input staged in smem in CIN chunks of 8 with halo; weights staged in smem.
template<int CIN, int COG, bool BIAS>
__global__ void __launch_bounds__(256)
conv3x3_kernel(const float* __restrict__ in, const float* __restrict__ w,
               const float* __restrict__ bias, float* __restrict__ out,
               int nGrp, int coutTotal)
{
    constexpr int TX = 32, TY = 32;
    constexpr int CCH = 8;
    __shared__ float s_in[CCH][TY + 2][TX + 3];   // row stride 35 (odd) -> no bank conflicts
    __shared__ float s_w[COG][CCH][9];

    const int bz = blockIdx.z;
    const int b = bz / nGrp;
    const int g = bz % nGrp;
    const int ox0 = blockIdx.x * TX;
    const int oy0 = blockIdx.y * TY;
    const int tid = threadIdx.x;
    const int txi = tid & 15;          // 16 thread columns
    const int tyi = tid >> 4;          // 16 thread rows
    const int lx = txi * 2;            // local output x (within tile)
    const int ly = tyi * 2;            // local output y

    const float* inb = in + (size_t)b * CIN * HWP;

    float acc[COG][4];
    #pragma unroll
    for (int o = 0; o < COG; o++) {
        acc[o][0] = 0.f; acc[o][1] = 0.f; acc[o][2] = 0.f; acc[o][3] = 0.f;
    }

    for (int c0 = 0; c0 < CIN; c0 += CCH) {
        __syncthreads();
        // stage input chunk with halo
        for (int i = tid; i < CCH * (TY + 2) * (TX + 2); i += 256) {
            int ci = i / ((TY + 2) * (TX + 2));
            int r  = i % ((TY + 2) * (TX + 2));
            int yy = r / (TX + 2);
            int xx = r % (TX + 2);
            int gy = oy0 + yy - 1;
            int gx = ox0 + xx - 1;
            float v = 0.f;
            if (gy >= 0 && gy < H64 && gx >= 0 && gx < W64)
                v = inb[(size_t)(c0 + ci) * HWP + gy * W64 + gx];
            s_in[ci][yy][xx] = v;
        }
        // stage weights: w layout (coutTotal, CIN, 3, 3)
        for (int i = tid; i < COG * CCH * 9; i += 256) {
            int lco = i / (CCH * 9);
            int r   = i % (CCH * 9);
            int ci  = r / 9;
            int k   = r % 9;
            s_w[lco][ci][k] = w[((size_t)(g * COG + lco) * CIN + (c0 + ci)) * 9 + k];
        }
        __syncthreads();

        #pragma unroll 1
        for (int ci = 0; ci < CCH; ci++) {
            #pragma unroll
            for (int ky = 0; ky < 3; ky++) {
                #pragma unroll
                for (int kx = 0; kx < 3; kx++) {
                    float i00 = s_in[ci][ly + ky    ][lx + kx    ];
                    float i01 = s_in[ci][ly + ky    ][lx + kx + 1];
                    float i10 = s_in[ci][ly + ky + 1][lx + kx    ];
                    float i11 = s_in[ci][ly + ky + 1][lx + kx + 1];
                    #pragma unroll
                    for (int o = 0; o < COG; o++) {
                        float wv = s_w[o][ci][ky * 3 + kx];
                        acc[o][0] = fmaf(wv, i00, acc[o][0]);
                        acc[o][1] = fmaf(wv, i01, acc[o][1]);
                        acc[o][2] = fmaf(wv, i10, acc[o][2]);
                        acc[o][3] = fmaf(wv, i11, acc[o][3]);
                    }
                }
            }
        }
    }

    const int oy = oy0 + ly;
    const int ox = ox0 + lx;
    #pragma unroll
    for (int o = 0; o < COG; o++) {
        int co = g * COG + o;
        float bv = BIAS ? bias[co] : 0.f;
        float* op = out + ((size_t)b * coutTotal + co) * HWP;
        op[oy * W64 + ox]           = acc[o][0] + bv;
        op[oy * W64 + ox + 1]       = acc[o][1] + bv;
        op[(oy + 1) * W64 + ox]     = acc[o][2] + bv;
        op[(oy + 1) * W64 + ox + 1] = acc[o][3] + bv;
    }
}

// ---------------- 1x1 conv, 64 -> 16 ----------------
__global__ void __launch_bounds__(256)
conv1x1_kernel(const float* __restrict__ in, const float* __restrict__ w,
               float* __restrict__ out)
{
    __shared__ float s_w[64][16];   // [ci][co]
    const int tid = threadIdx.x;
    for (int i = tid; i < 1024; i += 256) {
        int co = i / 64, ci = i % 64;
        s_w[ci][co] = w[co * 64 + ci];
    }
    __syncthreads();

    const int b = blockIdx.y;
    const int p = blockIdx.x * 256 + tid;
    const float* inb = in + (size_t)b * 64 * HWP + p;
    float acc[16];
    #pragma unroll
    for (int co = 0; co < 16; co++) acc[co] = 0.f;

    #pragma unroll 4
    for (int ci = 0; ci < 64; ci++) {
        float v = inb[(size_t)ci * HWP];
        #pragma unroll
        for (int co = 0; co < 16; co++) acc[co] = fmaf(v, s_w[ci][co], acc[co]);
    }
    float* ob = out + (size_t)b * 16 * HWP + p;
    #pragma unroll
    for (int co = 0; co < 16; co++) ob[(size_t)co * HWP] = acc[co];
}

// ---------------- per-channel sum / sumsq over (N,H,W) ----------------
__global__ void stats_kernel(const float* __restrict__ x, float* s1, float* s2, int CHW)
{
    const int c = blockIdx.x;
    float a = 0.f, q = 0.f;
    const int stride = gridDim.y * blockDim.x;
    for (int idx = blockIdx.y * blockDim.x + threadIdx.x; idx < NB * HWP; idx += stride) {
        int bb = idx >> 12;
        int hw = idx & 4095;
        float v = x[(size_t)bb * CHW + (size_t)c * HWP + hw];
        a += v;
        q = fmaf(v, v, q);
    }
    a = warp_sum(a); q = warp_sum(q);
    __shared__ float sa[8], sq[8];
    int lane = threadIdx.x & 31, wid = threadIdx.x >> 5;
    if (lane == 0) { sa[wid] = a; sq[wid] = q; }
    __syncthreads();
    if (wid == 0) {
        a = (lane < 8) ? sa[lane] : 0.f;
        q = (lane < 8) ? sq[lane] : 0.f;
        a = warp_sum(a); q = warp_sum(q);
        if (lane == 0) { atomicAdd(&s1[c], a); atomicAdd(&s2[c], q); }
    }
}

// ---------------- BN scale/shift from stats ----------------
__global__ void bnparam_kernel(const float* s1, const float* s2,
                               const float* g, const float* be,
                               float* a, float* b, int C)
{
    int c = threadIdx.x;
    if (c < C) {
        const float invN = 1.0f / (float)(NB * HWP);
        float m   = s1[c] * invN;
        float var = s2[c] * invN - m * m;
        float sc  = g[c] * rsqrtf(var + 1e-5f);
        a[c] = sc;
        b[c] = be[c] - m * sc;
    }
}

// ---------------- in-place BN + ReLU ----------------
__global__ void bnapply_relu_kernel(float* x, const float* __restrict__ a,
                                    const float* __restrict__ b, int cmask, int total)
{
    int i = blockIdx.x * blockDim.x + threadIdx.x;
    if (i < total) {
        int c = (i >> 12) & cmask;
        x[i] = fmaxf(fmaf(x[i], a[c], b[c]), 0.f);
    }
}

// ---------------- BN + residual + ReLU -> output ----------------
__global__ void resid_kernel(const float* __restrict__ y, const float* __restrict__ x,
                             const float* __restrict__ a, const float* __restrict__ b,
                             float* __restrict__ out, int total)
{
    int i = blockIdx.x * blockDim.x + threadIdx.x;
    if (i < total) {
        int c = (i >> 12) & 63;
        out[i] = fmaxf(fmaf(y[i], a[c], b[c]) + x[i], 0.f);
    }
}

// ---------------- deformable 3x3 conv, 16 -> 16, pad=1 ----------------
// Matches the JAX reference: pad input with zeros (pad=1), sampling coords clipped
// to [0, 65]; bilinear on the padded (zero-border) image.
__global__ void __launch_bounds__(256)
deform_kernel(const float* __restrict__ x, const float* __restrict__ off,
              const float* __restrict__ w, float* __restrict__ out)
{
    __shared__ float s_w[9][16][16];   // [k][cin][cout]
    const int tid = threadIdx.x;
    for (int i = tid; i < 2304; i += 256) {
        int o = i / 144;
        int r = i % 144;
        int c = r / 9;
        int k = r % 9;
        s_w[k][c][o] = w[i];           // w flat = ((o*16+c)*9+k)
    }
    __syncthreads();

    const int b  = blockIdx.z;
    const int ox = blockIdx.x * 16 + (tid & 15);
    const int oy = blockIdx.y * 16 + (tid >> 4);

    const float* xb   = x   + (size_t)b * 16 * HWP;
    const float* offb = off + (size_t)b * 18 * HWP + oy * W64 + ox;

    float acc[16];
    #pragma unroll
    for (int o = 0; o < 16; o++) acc[o] = 0.f;

    #pragma unroll 1
    for (int k = 0; k < 9; k++) {
        int ky = k / 3, kx = k % 3;
        // padded coords: p0 = (oy+1, ox+1), tap = (ky-1, kx-1)
        float py = (float)(oy + ky) + offb[(size_t)k * HWP];
        float px = (float)(ox + kx) + offb[(size_t)(9 + k) * HWP];
        py = fminf(fmaxf(py, 0.f), 65.f);
        px = fminf(fmaxf(px, 0.f), 65.f);
        float fy = floorf(py), fx = floorf(px);
        int y0 = (int)fy, x0 = (int)fx;
        int y1 = min(y0 + 1, 65), x1 = min(x0 + 1, 65);
        float wy = py - fy, wx = px - fx;
        float w00 = (1.f - wy) * (1.f - wx);
        float w01 = (1.f - wy) * wx;
        float w10 = wy * (1.f - wx);
        float w11 = wy * wx;
        bool vy0 = (y0 >= 1 && y0 <= 64);
        bool vy1 = (y1 >= 1 && y1 <= 64);
        bool vx0 = (x0 >= 1 && x0 <= 64);
        bool vx1 = (x1 >= 1 && x1 <= 64);
        int iy0 = (y0 - 1) * W64, iy1 = (y1 - 1) * W64;
        int ix0 = x0 - 1, ix1 = x1 - 1;

        #pragma unroll 1
        for (int c = 0; c < 16; c++) {
            const float* xc = xb + (size_t)c * HWP;
            float v00 = (vy0 && vx0) ? __ldg(xc + iy0 + ix0) : 0.f;
            float v01 = (vy0 && vx1) ? __ldg(xc + iy0 + ix1) : 0.f;
            float v10 = (vy1 && vx0) ? __ldg(xc + iy1 + ix0) : 0.f;
            float v11 = (vy1 && vx1) ? __ldg(xc + iy1 + ix1) : 0.f;
            float s = fmaf(v00, w00, fmaf(v01, w01, fmaf(v10, w10, v11 * w11)));
            #pragma unroll
            for (int o = 0; o < 16; o++) acc[o] = fmaf(s, s_w[k][c][o], acc[o]);
        }
    }

    float* ob = out + (size_t)b * 16 * HWP + oy * W64 + ox;
    #pragma unroll
    for (int o = 0; o < 16; o++) ob[(size_t)o * HWP] = acc[o];
}

// ---------------- launch ----------------
extern "C" void kernel_launch(void* const* d_in, const int* in_sizes, int n_in,
                              void* d_out, int out_size)
{
    const float* x    = (const float*)d_in[0];
    const float* c1w  = (const float*)d_in[1];
    const float* bn1g = (const float*)d_in[2];
    const float* bn1b = (const float*)d_in[3];
    const float* c2w  = (const float*)d_in[4];
    const float* bn2g = (const float*)d_in[5];
    const float* bn2b = (const float*)d_in[6];
    const float* offw = (const float*)d_in[7];
    const float* offb = (const float*)d_in[8];
    const float* c3w  = (const float*)d_in[9];
    const float* bn3g = (const float*)d_in[10];
    const float* bn3b = (const float*)d_in[11];
    const float* c4w  = (const float*)d_in[12];
    const float* bn4g = (const float*)d_in[13];
    const float* bn4b = (const float*)d_in[14];
    float* out = (float*)d_out;

    float *buf1, *buf2, *offs, *buf3, *buf4, *stats, *bnp;
    cudaGetSymbolAddress((void**)&buf1,  g_buf1);
    cudaGetSymbolAddress((void**)&buf2,  g_buf2);
    cudaGetSymbolAddress((void**)&offs,  g_offs);
    cudaGetSymbolAddress((void**)&buf3,  g_buf3);
    cudaGetSymbolAddress((void**)&buf4,  g_buf4);
    cudaGetSymbolAddress((void**)&stats, g_stats);
    cudaGetSymbolAddress((void**)&bnp,   g_bnp);

    const int TOT64 = NB * 64 * HWP;   // 16,777,216
    const int TOT16 = NB * 16 * HWP;   //  4,194,304

    zero_stats_kernel<<<1, 320>>>(stats);

    // stage 1: conv1 (64->64) + BN + ReLU   [grid.x=2, grid.y=2 covers full 64x64]
    conv3x3_kernel<64, 16, false><<<dim3(2, 2, NB * 4), 256>>>(x, c1w, nullptr, buf1, 4, 64);
    stats_kernel<<<dim3(64, 16), 256>>>(buf1, stats + 0, stats + 64, 64 * HWP);
    bnparam_kernel<<<1, 64>>>(stats + 0, stats + 64, bn1g, bn1b, bnp + 0, bnp + 64, 64);
    bnapply_relu_kernel<<<(TOT64 + 255) / 256, 256>>>(buf1, bnp + 0, bnp + 64, 63, TOT64);

    // stage 2: conv2 1x1 (64->16) + BN + ReLU
    conv1x1_kernel<<<dim3(16, NB), 256>>>(buf1, c2w, buf2);
    stats_kernel<<<dim3(16, 16), 256>>>(buf2, stats + 128, stats + 144, 16 * HWP);
    bnparam_kernel<<<1, 16>>>(stats + 128, stats + 144, bn2g, bn2b, bnp + 128, bnp + 144, 16);
    bnapply_relu_kernel<<<(TOT16 + 255) / 256, 256>>>(buf2, bnp + 128, bnp + 144, 15, TOT16);

    // stage 3: offset conv (16->18, +bias), deformable conv (16->16) + BN + ReLU
    conv3x3_kernel<16, 18, true><<<dim3(2, 2, NB), 256>>>(buf2, offw, offb, offs, 1, 18);
    deform_kernel<<<dim3(4, 4, NB), 256>>>(buf2, offs, c3w, buf3);
    stats_kernel<<<dim3(16, 16), 256>>>(buf3, stats + 160, stats + 176, 16 * HWP);
    bnparam_kernel<<<1, 16>>>(stats + 160, stats + 176, bn3g, bn3b, bnp + 160, bnp + 176, 16);
    bnapply_relu_kernel<<<(TOT16 + 255) / 256, 256>>>(buf3, bnp + 160, bnp + 176, 15, TOT16);

    // stage 4: conv4 (16->64) + BN + residual + ReLU
    conv3x3_kernel<16, 16, false><<<dim3(2, 2, NB * 4), 256>>>(buf3, c4w, nullptr, buf4, 4, 64);
    stats_kernel<<<dim3(64, 16), 256>>>(buf4, stats + 192, stats + 256, 64 * HWP);
    bnparam_kernel<<<1, 64>>>(stats + 192, stats + 256, bn4g, bn4b, bnp + 192, bnp + 256, 64);
    resid_kernel<<<(TOT64 + 255) / 256, 256>>>(buf4, x, bnp + 192, bnp + 256, out, TOT64);
}

// round 9
// speedup vs baseline: 1.4852x; 1.4852x over previous
#include <cuda_runtime.h>
#include <math.h>
#include <stdint.h>

// Problem constants
#define NB   64     // batch
#define H64  64
#define W64  64
#define HWP  4096   // 64*64

typedef unsigned long long u64;

// ---------------- scratch (device globals; no allocation allowed) ----------------
__device__ float g_buf1[(size_t)NB * 64 * HWP];   // conv1 out (raw)
__device__ float g_buf2[(size_t)NB * 16 * HWP];   // conv2 out (raw, then BN+ReLU in place)
__device__ float g_offs[(size_t)NB * 18 * HWP];   // offset conv out
__device__ float g_buf3[(size_t)NB * 16 * HWP];   // deform conv out (raw)
__device__ float g_buf4[(size_t)NB * 64 * HWP];   // conv4 out (raw)
__device__ float g_stats[320];                    // per-stage sum / sumsq
__device__ float g_bnp[320];                      // per-stage scale / shift

// stats/bnp layout: [0:64]=st1 sum, [64:128]=st1 sq, [128:144]=st2 sum,
// [144:160]=st2 sq, [160:176]=st3 sum, [176:192]=st3 sq,
// [192:256]=st4 sum, [256:320]=st4 sq

// ---------------- helpers ----------------
__device__ __forceinline__ float warp_sum(float v) {
    #pragma unroll
    for (int s = 16; s > 0; s >>= 1) v += __shfl_xor_sync(0xffffffffu, v, s);
    return v;
}

// packed fp32x2 (Blackwell FFMA2 — 2x fp32 FMA rate, only reachable via PTX)
__device__ __forceinline__ u64 dup2(float v) {
    u64 r; asm("mov.b64 %0, {%1, %1};" : "=l"(r) : "f"(v)); return r;
}
__device__ __forceinline__ void fma2(u64& d, u64 a, u64 b) {
    asm("fma.rn.f32x2 %0, %1, %2, %0;" : "+l"(d) : "l"(a), "l"(b));
}
__device__ __forceinline__ float2 unpk(u64 v) {
    float2 f; asm("mov.b64 {%0, %1}, %2;" : "=f"(f.x), "=f"(f.y) : "l"(v)); return f;
}

__global__ void zero_stats_kernel(float* s) {
    s[threadIdx.x] = 0.0f;   // 320 threads
}

// ---------------- direct 3x3 conv, pad=1, stride=1, f32x2 math ----------------
// Tile: 32x32 outputs per block, 256 threads, each thread 2x2 pixels x COG channels
// (COG/2 packed channel-pairs). Optional fused BN+ReLU on input load (in-bounds
// cells ONLY — pad stays exactly 0, matching conv2d's zero padding of the BN
// output), optional per-channel sum/sumsq epilogue.
template<int CIN, int COG, bool BIAS, bool INBN, bool STATS>
__global__ void __launch_bounds__(256)
conv3x3_kernel(const float* __restrict__ in, const float* __restrict__ w,
               const float* __restrict__ bias,
               const float* __restrict__ abn, const float* __restrict__ bbn,
               float* __restrict__ out, float* s1, float* s2,
               int nGrp, int coutTotal)
{
    constexpr int TX = 32, TY = 32, CCH = 8;
    constexpr int OP = COG / 2;
    __shared__ __align__(16) float s_in[CCH][TY + 2][TX + 4];   // row stride 36
    __shared__ __align__(16) float s_w[CCH][9][COG];            // o contiguous
    __shared__ float s_a[CIN], s_b[CIN];
    __shared__ float s_red[8][COG][2];

    const int bz = blockIdx.z;
    const int b = bz / nGrp;
    const int g = bz % nGrp;
    const int ox0 = blockIdx.x * TX;
    const int oy0 = blockIdx.y * TY;
    const int tid = threadIdx.x;
    const int lx = (tid & 15) * 2;
    const int ly = (tid >> 4) * 2;

    const float* inb = in + (size_t)b * CIN * HWP;

    if (INBN) {
        for (int i = tid; i < CIN; i += 256) { s_a[i] = abn[i]; s_b[i] = bbn[i]; }
    }

    u64 accp[OP][4];
    #pragma unroll
    for (int p = 0; p < OP; p++) {
        accp[p][0] = 0ull; accp[p][1] = 0ull; accp[p][2] = 0ull; accp[p][3] = 0ull;
    }

    for (int c0 = 0; c0 < CIN; c0 += CCH) {
        __syncthreads();
        // stage input chunk with halo (+ fused BN+ReLU on in-bounds cells only)
        for (int i = tid; i < CCH * 34 * 34; i += 256) {
            int ci = i / (34 * 34);
            int r  = i % (34 * 34);
            int yy = r / 34;
            int xx = r % 34;
            int gy = oy0 + yy - 1;
            int gx = ox0 + xx - 1;
            float v = 0.f;
            if (gy >= 0 && gy < H64 && gx >= 0 && gx < W64) {
                v = inb[(size_t)(c0 + ci) * HWP + gy * W64 + gx];
                if (INBN) v = fmaxf(fmaf(v, s_a[c0 + ci], s_b[c0 + ci]), 0.f);
            }
            s_in[ci][yy][xx] = v;
        }
        // stage weights: w layout (coutTotal, CIN, 3, 3) -> s_w[ci][k][lco]
        for (int i = tid; i < CCH * 9 * COG; i += 256) {
            int ci  = i / (9 * COG);
            int r   = i % (9 * COG);
            int k   = r / COG;
            int lco = r % COG;
            int co  = g * COG + lco;
            s_w[ci][k][lco] = (co < coutTotal)
                ? w[((size_t)co * CIN + (c0 + ci)) * 9 + k] : 0.f;
        }
        __syncthreads();

        #pragma unroll 1
        for (int ci = 0; ci < CCH; ci++) {
            // 4x4 input patch in registers (float2 smem loads, conflict-free)
            float r4[4][4];
            #pragma unroll
            for (int y = 0; y < 4; y++) {
                float2 t0 = *(const float2*)&s_in[ci][ly + y][lx];
                float2 t1 = *(const float2*)&s_in[ci][ly + y][lx + 2];
                r4[y][0] = t0.x; r4[y][1] = t0.y; r4[y][2] = t1.x; r4[y][3] = t1.y;
            }
            #pragma unroll
            for (int ky = 0; ky < 3; ky++) {
                #pragma unroll
                for (int kx = 0; kx < 3; kx++) {
                    const int k = ky * 3 + kx;
                    u64 I0 = dup2(r4[ky    ][kx    ]);
                    u64 I1 = dup2(r4[ky    ][kx + 1]);
                    u64 I2 = dup2(r4[ky + 1][kx    ]);
                    u64 I3 = dup2(r4[ky + 1][kx + 1]);
                    #pragma unroll
                    for (int oq = 0; oq < COG / 4; oq++) {
                        ulonglong2 wv = *(const ulonglong2*)&s_w[ci][k][4 * oq];
                        fma2(accp[2 * oq    ][0], wv.x, I0);
                        fma2(accp[2 * oq    ][1], wv.x, I1);
                        fma2(accp[2 * oq    ][2], wv.x, I2);
                        fma2(accp[2 * oq    ][3], wv.x, I3);
                        fma2(accp[2 * oq + 1][0], wv.y, I0);
                        fma2(accp[2 * oq + 1][1], wv.y, I1);
                        fma2(accp[2 * oq + 1][2], wv.y, I2);
                        fma2(accp[2 * oq + 1][3], wv.y, I3);
                    }
                }
            }
        }
    }

    // ---------------- epilogue: store (+bias), optional stats ----------------
    const int oy = oy0 + ly;
    const int ox = ox0 + lx;
    const int lane = tid & 31, wrp = tid >> 5;

    #pragma unroll
    for (int p = 0; p < OP; p++) {
        float2 v0 = unpk(accp[p][0]);
        float2 v1 = unpk(accp[p][1]);
        float2 v2 = unpk(accp[p][2]);
        float2 v3 = unpk(accp[p][3]);
        int co0 = g * COG + 2 * p;
        int co1 = co0 + 1;
        if (co0 < coutTotal) {
            float bv = BIAS ? bias[co0] : 0.f;
            float* op = out + ((size_t)b * coutTotal + co0) * HWP;
            op[oy * W64 + ox]           = v0.x + bv;
            op[oy * W64 + ox + 1]       = v1.x + bv;
            op[(oy + 1) * W64 + ox]     = v2.x + bv;
            op[(oy + 1) * W64 + ox + 1] = v3.x + bv;
        }
        if (co1 < coutTotal) {
            float bv = BIAS ? bias[co1] : 0.f;
            float* op = out + ((size_t)b * coutTotal + co1) * HWP;
            op[oy * W64 + ox]           = v0.y + bv;
            op[oy * W64 + ox + 1]       = v1.y + bv;
            op[(oy + 1) * W64 + ox]     = v2.y + bv;
            op[(oy + 1) * W64 + ox + 1] = v3.y + bv;
        }
        if (STATS) {
            float ls0 = v0.x + v1.x + v2.x + v3.x;
            float lq0 = fmaf(v0.x, v0.x, fmaf(v1.x, v1.x, fmaf(v2.x, v2.x, v3.x * v3.x)));
            float ls1 = v0.y + v1.y + v2.y + v3.y;
            float lq1 = fmaf(v0.y, v0.y, fmaf(v1.y, v1.y, fmaf(v2.y, v2.y, v3.y * v3.y)));
            ls0 = warp_sum(ls0); lq0 = warp_sum(lq0);
            ls1 = warp_sum(ls1); lq1 = warp_sum(lq1);
            if (lane == 0) {
                s_red[wrp][2 * p][0] = ls0; s_red[wrp][2 * p][1] = lq0;
                s_red[wrp][2 * p + 1][0] = ls1; s_red[wrp][2 * p + 1][1] = lq1;
            }
        }
    }
    if (STATS) {
        __syncthreads();
        if (tid < COG) {
            float A = 0.f, Q = 0.f;
            #pragma unroll
            for (int w8 = 0; w8 < 8; w8++) { A += s_red[w8][tid][0]; Q += s_red[w8][tid][1]; }
            int co = g * COG + tid;
            if (co < coutTotal) { atomicAdd(&s1[co], A); atomicAdd(&s2[co], Q); }
        }
    }
}

// ---------------- 1x1 conv, 64 -> 16, fused BN1+ReLU on load, stats epilogue ----------------
__global__ void __launch_bounds__(256)
conv1x1_kernel(const float* __restrict__ in, const float* __restrict__ w,
               const float* __restrict__ abn, const float* __restrict__ bbn,
               float* __restrict__ out, float* s1, float* s2)
{
    __shared__ float s_w[64][16];   // [ci][co]
    __shared__ float s_a[64], s_b[64];
    __shared__ float s_red[8][16][2];
    const int tid = threadIdx.x;
    for (int i = tid; i < 1024; i += 256) {
        int co = i / 64, ci = i % 64;
        s_w[ci][co] = w[co * 64 + ci];
    }
    for (int i = tid; i < 64; i += 256) { s_a[i] = abn[i]; s_b[i] = bbn[i]; }
    __syncthreads();

    const int b = blockIdx.y;
    const int p = blockIdx.x * 256 + tid;
    const float* inb = in + (size_t)b * 64 * HWP + p;
    float acc[16];
    #pragma unroll
    for (int co = 0; co < 16; co++) acc[co] = 0.f;

    #pragma unroll 4
    for (int ci = 0; ci < 64; ci++) {
        float v = inb[(size_t)ci * HWP];
        v = fmaxf(fmaf(v, s_a[ci], s_b[ci]), 0.f);   // BN1 + ReLU fused (1x1: no padding)
        #pragma unroll
        for (int co = 0; co < 16; co++) acc[co] = fmaf(v, s_w[ci][co], acc[co]);
    }
    float* ob = out + (size_t)b * 16 * HWP + p;
    const int lane = tid & 31, wrp = tid >> 5;
    #pragma unroll
    for (int co = 0; co < 16; co++) {
        ob[(size_t)co * HWP] = acc[co];
        float ls = warp_sum(acc[co]);
        float lq = warp_sum(acc[co] * acc[co]);
        if (lane == 0) { s_red[wrp][co][0] = ls; s_red[wrp][co][1] = lq; }
    }
    __syncthreads();
    if (tid < 16) {
        float A = 0.f, Q = 0.f;
        #pragma unroll
        for (int w8 = 0; w8 < 8; w8++) { A += s_red[w8][tid][0]; Q += s_red[w8][tid][1]; }
        atomicAdd(&s1[tid], A); atomicAdd(&s2[tid], Q);
    }
}

// ---------------- BN scale/shift from stats ----------------
__global__ void bnparam_kernel(const float* s1, const float* s2,
                               const float* g, const float* be,
                               float* a, float* b, int C)
{
    int c = threadIdx.x;
    if (c < C) {
        const float invN = 1.0f / (float)(NB * HWP);
        float m   = s1[c] * invN;
        float var = s2[c] * invN - m * m;
        float sc  = g[c] * rsqrtf(var + 1e-5f);
        a[c] = sc;
        b[c] = be[c] - m * sc;
    }
}

// ---------------- in-place BN + ReLU (float4) ----------------
__global__ void bnapply4_kernel(float4* x, const float* __restrict__ a,
                                const float* __restrict__ b, int cmask, int total4)
{
    int i = blockIdx.x * blockDim.x + threadIdx.x;
    if (i < total4) {
        int c = (i >> 10) & cmask;
        float4 v = x[i];
        float sa = a[c], sb = b[c];
        v.x = fmaxf(fmaf(v.x, sa, sb), 0.f);
        v.y = fmaxf(fmaf(v.y, sa, sb), 0.f);
        v.z = fmaxf(fmaf(v.z, sa, sb), 0.f);
        v.w = fmaxf(fmaf(v.w, sa, sb), 0.f);
        x[i] = v;
    }
}

// ---------------- BN + residual + ReLU -> output (float4) ----------------
__global__ void resid4_kernel(const float4* __restrict__ y, const float4* __restrict__ x,
                              const float* __restrict__ a, const float* __restrict__ b,
                              float4* __restrict__ out, int total4)
{
    int i = blockIdx.x * blockDim.x + threadIdx.x;
    if (i < total4) {
        int c = (i >> 10) & 63;
        float4 v = y[i], r = x[i], o;
        float sa = a[c], sb = b[c];
        o.x = fmaxf(fmaf(v.x, sa, sb) + r.x, 0.f);
        o.y = fmaxf(fmaf(v.y, sa, sb) + r.y, 0.f);
        o.z = fmaxf(fmaf(v.z, sa, sb) + r.z, 0.f);
        o.w = fmaxf(fmaf(v.w, sa, sb) + r.w, 0.f);
        out[i] = o;
    }
}

// ---------------- deformable 3x3 conv, 16 -> 16, pad=1, f32x2 + stats ----------------
// Matches the JAX reference: zero-padded image (pad=1), coords clipped to [0,65],
// bilinear on the padded image.
__global__ void __launch_bounds__(256)
deform_kernel(const float* __restrict__ x, const float* __restrict__ off,
              const float* __restrict__ w, float* __restrict__ out,
              float* s1, float* s2)
{
    __shared__ __align__(16) float s_w[9][16][16];   // [k][cin][cout], cout contiguous
    __shared__ float s_red[8][16][2];
    const int tid = threadIdx.x;
    for (int i = tid; i < 2304; i += 256) {
        int o = i / 144;
        int r = i % 144;
        int c = r / 9;
        int k = r % 9;
        s_w[k][c][o] = w[i];           // w flat = ((o*16+c)*9+k)
    }
    __syncthreads();

    const int b  = blockIdx.z;
    const int ox = blockIdx.x * 16 + (tid & 15);
    const int oy = blockIdx.y * 16 + (tid >> 4);

    const float* xb   = x   + (size_t)b * 16 * HWP;
    const float* offb = off + (size_t)b * 18 * HWP + oy * W64 + ox;

    u64 accp[8];
    #pragma unroll
    for (int p = 0; p < 8; p++) accp[p] = 0ull;

    #pragma unroll 1
    for (int k = 0; k < 9; k++) {
        int ky = k / 3, kx = k % 3;
        // padded coords: p0 = (oy+1, ox+1), tap = (ky-1, kx-1)
        float py = (float)(oy + ky) + offb[(size_t)k * HWP];
        float px = (float)(ox + kx) + offb[(size_t)(9 + k) * HWP];
        py = fminf(fmaxf(py, 0.f), 65.f);
        px = fminf(fmaxf(px, 0.f), 65.f);
        float fy = floorf(py), fx = floorf(px);
        int y0 = (int)fy, x0 = (int)fx;
        int y1 = min(y0 + 1, 65), x1 = min(x0 + 1, 65);
        float wy = py - fy, wx = px - fx;
        float w00 = (1.f - wy) * (1.f - wx);
        float w01 = (1.f - wy) * wx;
        float w10 = wy * (1.f - wx);
        float w11 = wy * wx;
        bool vy0 = (y0 >= 1 && y0 <= 64);
        bool vy1 = (y1 >= 1 && y1 <= 64);
        bool vx0 = (x0 >= 1 && x0 <= 64);
        bool vx1 = (x1 >= 1 && x1 <= 64);
        int iy0 = (y0 - 1) * W64, iy1 = (y1 - 1) * W64;
        int ix0 = x0 - 1, ix1 = x1 - 1;

        #pragma unroll 1
        for (int c = 0; c < 16; c++) {
            const float* xc = xb + (size_t)c * HWP;
            float v00 = (vy0 && vx0) ? __ldg(xc + iy0 + ix0) : 0.f;
            float v01 = (vy0 && vx1) ? __ldg(xc + iy0 + ix1) : 0.f;
            float v10 = (vy1 && vx0) ? __ldg(xc + iy1 + ix0) : 0.f;
            float v11 = (vy1 && vx1) ? __ldg(xc + iy1 + ix1) : 0.f;
            float s = fmaf(v00, w00, fmaf(v01, w01, fmaf(v10, w10, v11 * w11)));
            u64 S = dup2(s);
            ulonglong2 wa = *(const ulonglong2*)&s_w[k][c][0];
            ulonglong2 wb = *(const ulonglong2*)&s_w[k][c][4];
            ulonglong2 wc = *(const ulonglong2*)&s_w[k][c][8];
            ulonglong2 wd = *(const ulonglong2*)&s_w[k][c][12];
            fma2(accp[0], wa.x, S); fma2(accp[1], wa.y, S);
            fma2(accp[2], wb.x, S); fma2(accp[3], wb.y, S);
            fma2(accp[4], wc.x, S); fma2(accp[5], wc.y, S);
            fma2(accp[6], wd.x, S); fma2(accp[7], wd.y, S);
        }
    }

    float* ob = out + (size_t)b * 16 * HWP + oy * W64 + ox;
    const int lane = tid & 31, wrp = tid >> 5;
    #pragma unroll
    for (int p = 0; p < 8; p++) {
        float2 v = unpk(accp[p]);
        ob[(size_t)(2 * p) * HWP]     = v.x;
        ob[(size_t)(2 * p + 1) * HWP] = v.y;
        float ls0 = warp_sum(v.x);
        float lq0 = warp_sum(v.x * v.x);
        float ls1 = warp_sum(v.y);
        float lq1 = warp_sum(v.y * v.y);
        if (lane == 0) {
            s_red[wrp][2 * p][0] = ls0;     s_red[wrp][2 * p][1] = lq0;
            s_red[wrp][2 * p + 1][0] = ls1; s_red[wrp][2 * p + 1][1] = lq1;
        }
    }
    __syncthreads();
    if (tid < 16) {
        float A = 0.f, Q = 0.f;
        #pragma unroll
        for (int w8 = 0; w8 < 8; w8++) { A += s_red[w8][tid][0]; Q += s_red[w8][tid][1]; }
        atomicAdd(&s1[tid], A); atomicAdd(&s2[tid], Q);
    }
}

// ---------------- launch ----------------
extern "C" void kernel_launch(void* const* d_in, const int* in_sizes, int n_in,
                              void* d_out, int out_size)
{
    const float* x    = (const float*)d_in[0];
    const float* c1w  = (const float*)d_in[1];
    const float* bn1g = (const float*)d_in[2];
    const float* bn1b = (const float*)d_in[3];
    const float* c2w  = (const float*)d_in[4];
    const float* bn2g = (const float*)d_in[5];
    const float* bn2b = (const float*)d_in[6];
    const float* offw = (const float*)d_in[7];
    const float* offb = (const float*)d_in[8];
    const float* c3w  = (const float*)d_in[9];
    const float* bn3g = (const float*)d_in[10];
    const float* bn3b = (const float*)d_in[11];
    const float* c4w  = (const float*)d_in[12];
    const float* bn4g = (const float*)d_in[13];
    const float* bn4b = (const float*)d_in[14];
    float* out = (float*)d_out;

    float *buf1, *buf2, *offs, *buf3, *buf4, *stats, *bnp;
    cudaGetSymbolAddress((void**)&buf1,  g_buf1);
    cudaGetSymbolAddress((void**)&buf2,  g_buf2);
    cudaGetSymbolAddress((void**)&offs,  g_offs);
    cudaGetSymbolAddress((void**)&buf3,  g_buf3);
    cudaGetSymbolAddress((void**)&buf4,  g_buf4);
    cudaGetSymbolAddress((void**)&stats, g_stats);
    cudaGetSymbolAddress((void**)&bnp,   g_bnp);

    const int TOT64 = NB * 64 * HWP;   // 16,777,216
    const int TOT16 = NB * 16 * HWP;   //  4,194,304

    zero_stats_kernel<<<1, 320>>>(stats);

    // stage 1: conv1 (64->64, raw) with fused stats epilogue
    conv3x3_kernel<64, 16, false, false, true><<<dim3(2, 2, NB * 4), 256>>>(
        x, c1w, nullptr, nullptr, nullptr, buf1, stats + 0, stats + 64, 4, 64);
    bnparam_kernel<<<1, 64>>>(stats + 0, stats + 64, bn1g, bn1b, bnp + 0, bnp + 64, 64);

    // stage 2: conv2 1x1 (BN1+ReLU fused on load) with fused stats epilogue
    conv1x1_kernel<<<dim3(16, NB), 256>>>(buf1, c2w, bnp + 0, bnp + 64,
                                          buf2, stats + 128, stats + 144);
    bnparam_kernel<<<1, 16>>>(stats + 128, stats + 144, bn2g, bn2b, bnp + 128, bnp + 144, 16);
    // materialize BN2+ReLU on buf2 (read many times by deform gathers)
    bnapply4_kernel<<<(TOT16 / 4 + 255) / 256, 256>>>((float4*)buf2, bnp + 128, bnp + 144,
                                                      15, TOT16 / 4);

    // stage 3: offset conv (16->18+bias, COG padded to 20), deform (+stats)
    conv3x3_kernel<16, 20, true, false, false><<<dim3(2, 2, NB), 256>>>(
        buf2, offw, offb, nullptr, nullptr, offs, nullptr, nullptr, 1, 18);
    deform_kernel<<<dim3(4, 4, NB), 256>>>(buf2, offs, c3w, buf3, stats + 160, stats + 176);
    bnparam_kernel<<<1, 16>>>(stats + 160, stats + 176, bn3g, bn3b, bnp + 160, bnp + 176, 16);

    // stage 4: conv4 (16->64, BN3+ReLU fused on in-bounds load) with fused stats epilogue
    conv3x3_kernel<16, 16, false, true, true><<<dim3(2, 2, NB * 4), 256>>>(
        buf3, c4w, nullptr, bnp + 160, bnp + 176, buf4, stats + 192, stats + 256, 4, 64);
    bnparam_kernel<<<1, 64>>>(stats + 192, stats + 256, bn4g, bn4b, bnp + 192, bnp + 256, 64);

    // residual + BN4 + ReLU
    resid4_kernel<<<(TOT64 / 4 + 255) / 256, 256>>>((const float4*)buf4, (const float4*)x,
                                                    bnp + 192, bnp + 256, (float4*)out, TOT64 / 4);
}

// round 10
// speedup vs baseline: 2.1486x; 1.4467x over previous
#include <cuda_runtime.h>
#include <math.h>
#include <stdint.h>

// Problem constants
#define NB   64     // batch
#define H64  64
#define W64  64
#define HWP  4096   // 64*64

typedef unsigned long long u64;

// ---------------- scratch (device globals; no allocation allowed) ----------------
__device__ float g_buf1[(size_t)NB * 64 * HWP];   // conv1 out (raw)
__device__ float g_buf2[(size_t)NB * 16 * HWP];   // conv2 out (raw, then BN+ReLU in place)
__device__ float g_offs[(size_t)NB * 18 * HWP];   // offset conv out
__device__ float g_buf3[(size_t)NB * 16 * HWP];   // deform conv out (raw)
__device__ float g_buf4[(size_t)NB * 64 * HWP];   // conv4 out (raw)
__device__ float g_stats[320];                    // per-stage sum / sumsq
__device__ float g_bnp[320];                      // per-stage scale / shift

// ---------------- helpers ----------------
__device__ __forceinline__ float warp_sum(float v) {
    #pragma unroll
    for (int s = 16; s > 0; s >>= 1) v += __shfl_xor_sync(0xffffffffu, v, s);
    return v;
}

// packed fp32x2 (FFMA2) — used by offconv / deform
__device__ __forceinline__ u64 dup2(float v) {
    u64 r; asm("mov.b64 %0, {%1, %1};" : "=l"(r) : "f"(v)); return r;
}
__device__ __forceinline__ void fma2(u64& d, u64 a, u64 b) {
    asm("fma.rn.f32x2 %0, %1, %2, %0;" : "+l"(d) : "l"(a), "l"(b));
}
__device__ __forceinline__ float2 unpk(u64 v) {
    float2 f; asm("mov.b64 {%0, %1}, %2;" : "=f"(f.x), "=f"(f.y) : "l"(v)); return f;
}

// tf32 round-to-nearest conversion
__device__ __forceinline__ uint32_t to_tf32(float f) {
    uint32_t r; asm("cvt.rna.tf32.f32 %0, %1;" : "=r"(r) : "f"(f)); return r;
}

// m16n8k8 tf32 MMA, fp32 accumulate
__device__ __forceinline__ void mma_tf32(float* d,
    uint32_t a0, uint32_t a1, uint32_t a2, uint32_t a3,
    uint32_t b0, uint32_t b1)
{
    asm volatile(
        "mma.sync.aligned.m16n8k8.row.col.f32.tf32.tf32.f32 "
        "{%0,%1,%2,%3}, {%4,%5,%6,%7}, {%8,%9}, {%0,%1,%2,%3};"
        : "+f"(d[0]), "+f"(d[1]), "+f"(d[2]), "+f"(d[3])
        : "r"(a0), "r"(a1), "r"(a2), "r"(a3), "r"(b0), "r"(b1));
}

__global__ void zero_stats_kernel(float* s) {
    s[threadIdx.x] = 0.0f;   // 320 threads
}

// ======================================================================
// 3x3 conv (pad=1) as 9 per-tap tf32 GEMMs, COUT=64.
// CTA: 256 threads / 8 warps; tile = 8 image rows x full width (64).
// Warp w owns row y0+w: 4 m-tiles of 16 pixels x 8 n-tiles of 8 cout.
// K = CIN*9, processed as ci-chunks of 16 (x 9 taps x 2 sub-chunks of 8).
// Optional fused BN+ReLU on input staging (in-bounds cells ONLY).
// Per-channel sum/sumsq epilogue always on.
// Dynamic smem: s_in 16x664 u32 + s_w 9x16x72 u32 = 83968 bytes.
// ======================================================================
#define MMA_SMEM_U32  (16 * 664 + 9 * 16 * 72)
#define MMA_SMEM_BYTES (MMA_SMEM_U32 * 4)

template<int CIN, bool INBN>
__global__ void __launch_bounds__(256, 1)
conv3x3_mma(const float* __restrict__ in, const float* __restrict__ w,
            const float* __restrict__ abn, const float* __restrict__ bbn,
            float* __restrict__ out, float* s1, float* s2)
{
    constexpr int NCH = CIN / 16;             // ci chunks of 16
    extern __shared__ uint32_t dynsm[];
    uint32_t* s_in = dynsm;                   // [ci][yy*66+xx], plane stride 664
    uint32_t* s_w  = dynsm + 16 * 664;        // [tap][ci][72]
    __shared__ float s_bn[2][CIN];
    __shared__ float s_red[8][64][2];

    const int b   = blockIdx.y;
    const int y0  = blockIdx.x * 8;
    const int tid = threadIdx.x;
    const int wid = tid >> 5;
    const int lane = tid & 31;
    const int g   = lane >> 2;                // 0..7
    const int tig = lane & 3;                 // 0..3

    const float* inb = in + (size_t)b * CIN * HWP;

    if (INBN) {
        for (int i = tid; i < CIN; i += 256) { s_bn[0][i] = abn[i]; s_bn[1][i] = bbn[i]; }
    }

    float acc[4][8][4];                       // [m-tile][n-tile][frag]
    #pragma unroll
    for (int mt = 0; mt < 4; mt++)
        #pragma unroll
        for (int nt = 0; nt < 8; nt++)
            #pragma unroll
            for (int r = 0; r < 4; r++) acc[mt][nt][r] = 0.f;

    for (int cc = 0; cc < NCH; cc++) {
        __syncthreads();
        // ---- stage input chunk: 16 ci x 10 rows x 66 cols, tf32-RNA ----
        for (int i = tid; i < 16 * 660; i += 256) {
            int ci = i / 660, r = i % 660, yy = r / 66, xx = r % 66;
            int gy = y0 + yy - 1, gx = xx - 1;
            float v = 0.f;
            if (gy >= 0 && gy < H64 && gx >= 0 && gx < W64) {
                v = inb[(size_t)(cc * 16 + ci) * HWP + gy * W64 + gx];
                if (INBN) v = fmaxf(fmaf(v, s_bn[0][cc * 16 + ci], s_bn[1][cc * 16 + ci]), 0.f);
            }
            s_in[ci * 664 + yy * 66 + xx] = to_tf32(v);
        }
        // ---- stage weights: w[(co*CIN + ci)*9 + tap] -> s_w[tap][ci][co] ----
        for (int i = tid; i < 9 * 16 * 64; i += 256) {
            int co = i & 63, ci = (i >> 6) & 15, tap = i >> 10;
            float v = w[((size_t)co * CIN + cc * 16 + ci) * 9 + tap];
            s_w[tap * (16 * 72) + ci * 72 + co] = to_tf32(v);
        }
        __syncthreads();

        #pragma unroll 1
        for (int tap = 0; tap < 9; tap++) {
            const int ky = tap / 3, kx = tap % 3;
            #pragma unroll
            for (int ks = 0; ks < 2; ks++) {
                // B fragments: k = ks*8 + tig (+4), n = nt*8 + g
                const uint32_t* wp = s_w + tap * (16 * 72) + (ks * 8 + tig) * 72;
                uint32_t bf0[8], bf1[8];
                #pragma unroll
                for (int nt = 0; nt < 8; nt++) {
                    bf0[nt] = wp[nt * 8 + g];
                    bf1[nt] = wp[4 * 72 + nt * 8 + g];
                }
                // A fragments: pixel row = y0+wid, x = mt*16 + g (+8); ci = ks*8 + tig (+4)
                const uint32_t* ip = s_in + (ks * 8 + tig) * 664 + (wid + ky) * 66 + kx;
                #pragma unroll
                for (int mt = 0; mt < 4; mt++) {
                    uint32_t a0 = ip[mt * 16 + g];
                    uint32_t a1 = ip[mt * 16 + g + 8];
                    uint32_t a2 = ip[4 * 664 + mt * 16 + g];
                    uint32_t a3 = ip[4 * 664 + mt * 16 + g + 8];
                    #pragma unroll
                    for (int nt = 0; nt < 8; nt++)
                        mma_tf32(acc[mt][nt], a0, a1, a2, a3, bf0[nt], bf1[nt]);
                }
            }
        }
    }

    // ---- epilogue: store + per-channel stats ----
    const int y = y0 + wid;
    float* ob = out + (size_t)b * 64 * HWP + y * W64;
    #pragma unroll
    for (int nt = 0; nt < 8; nt++) {
        const int co = nt * 8 + 2 * tig;
        float se = 0.f, qe = 0.f, so = 0.f, qo = 0.f;
        #pragma unroll
        for (int mt = 0; mt < 4; mt++) {
            const int x = mt * 16 + g;
            float c0 = acc[mt][nt][0], c1 = acc[mt][nt][1];
            float c2 = acc[mt][nt][2], c3 = acc[mt][nt][3];
            ob[(size_t)co * HWP + x]           = c0;   // row g,   col 2tig
            ob[(size_t)(co + 1) * HWP + x]     = c1;   // row g,   col 2tig+1
            ob[(size_t)co * HWP + x + 8]       = c2;   // row g+8, col 2tig
            ob[(size_t)(co + 1) * HWP + x + 8] = c3;
            se += c0 + c2; qe += fmaf(c0, c0, c2 * c2);
            so += c1 + c3; qo += fmaf(c1, c1, c3 * c3);
        }
        // reduce over g (lane bits 2..4)
        #pragma unroll
        for (int m = 4; m < 32; m <<= 1) {
            se += __shfl_xor_sync(0xffffffffu, se, m);
            qe += __shfl_xor_sync(0xffffffffu, qe, m);
            so += __shfl_xor_sync(0xffffffffu, so, m);
            qo += __shfl_xor_sync(0xffffffffu, qo, m);
        }
        if (g == 0) {
            s_red[wid][co][0] = se;     s_red[wid][co][1] = qe;
            s_red[wid][co + 1][0] = so; s_red[wid][co + 1][1] = qo;
        }
    }
    __syncthreads();
    if (tid < 64) {
        float A = 0.f, Q = 0.f;
        #pragma unroll
        for (int w8 = 0; w8 < 8; w8++) { A += s_red[w8][tid][0]; Q += s_red[w8][tid][1]; }
        atomicAdd(&s1[tid], A); atomicAdd(&s2[tid], Q);
    }
}

// ---------------- direct 3x3 conv (FFMA2) — used for the offset conv ----------------
template<int CIN, int COG, bool BIAS, bool INBN, bool STATS>
__global__ void __launch_bounds__(256)
conv3x3_kernel(const float* __restrict__ in, const float* __restrict__ w,
               const float* __restrict__ bias,
               const float* __restrict__ abn, const float* __restrict__ bbn,
               float* __restrict__ out, float* s1, float* s2,
               int nGrp, int coutTotal)
{
    constexpr int TX = 32, TY = 32, CCH = 8;
    constexpr int OP = COG / 2;
    __shared__ __align__(16) float s_in[CCH][TY + 2][TX + 4];
    __shared__ __align__(16) float s_w[CCH][9][COG];
    __shared__ float s_a[CIN], s_b[CIN];
    __shared__ float s_red[8][COG][2];

    const int bz = blockIdx.z;
    const int b = bz / nGrp;
    const int g = bz % nGrp;
    const int ox0 = blockIdx.x * TX;
    const int oy0 = blockIdx.y * TY;
    const int tid = threadIdx.x;
    const int lx = (tid & 15) * 2;
    const int ly = (tid >> 4) * 2;

    const float* inb = in + (size_t)b * CIN * HWP;

    if (INBN) {
        for (int i = tid; i < CIN; i += 256) { s_a[i] = abn[i]; s_b[i] = bbn[i]; }
    }

    u64 accp[OP][4];
    #pragma unroll
    for (int p = 0; p < OP; p++) {
        accp[p][0] = 0ull; accp[p][1] = 0ull; accp[p][2] = 0ull; accp[p][3] = 0ull;
    }

    for (int c0 = 0; c0 < CIN; c0 += CCH) {
        __syncthreads();
        for (int i = tid; i < CCH * 34 * 34; i += 256) {
            int ci = i / (34 * 34);
            int r  = i % (34 * 34);
            int yy = r / 34;
            int xx = r % 34;
            int gy = oy0 + yy - 1;
            int gx = ox0 + xx - 1;
            float v = 0.f;
            if (gy >= 0 && gy < H64 && gx >= 0 && gx < W64) {
                v = inb[(size_t)(c0 + ci) * HWP + gy * W64 + gx];
                if (INBN) v = fmaxf(fmaf(v, s_a[c0 + ci], s_b[c0 + ci]), 0.f);
            }
            s_in[ci][yy][xx] = v;
        }
        for (int i = tid; i < CCH * 9 * COG; i += 256) {
            int ci  = i / (9 * COG);
            int r   = i % (9 * COG);
            int k   = r / COG;
            int lco = r % COG;
            int co  = g * COG + lco;
            s_w[ci][k][lco] = (co < coutTotal)
                ? w[((size_t)co * CIN + (c0 + ci)) * 9 + k] : 0.f;
        }
        __syncthreads();

        #pragma unroll 1
        for (int ci = 0; ci < CCH; ci++) {
            float r4[4][4];
            #pragma unroll
            for (int y = 0; y < 4; y++) {
                float2 t0 = *(const float2*)&s_in[ci][ly + y][lx];
                float2 t1 = *(const float2*)&s_in[ci][ly + y][lx + 2];
                r4[y][0] = t0.x; r4[y][1] = t0.y; r4[y][2] = t1.x; r4[y][3] = t1.y;
            }
            #pragma unroll
            for (int ky = 0; ky < 3; ky++) {
                #pragma unroll
                for (int kx = 0; kx < 3; kx++) {
                    const int k = ky * 3 + kx;
                    u64 I0 = dup2(r4[ky    ][kx    ]);
                    u64 I1 = dup2(r4[ky    ][kx + 1]);
                    u64 I2 = dup2(r4[ky + 1][kx    ]);
                    u64 I3 = dup2(r4[ky + 1][kx + 1]);
                    #pragma unroll
                    for (int oq = 0; oq < COG / 4; oq++) {
                        ulonglong2 wv = *(const ulonglong2*)&s_w[ci][k][4 * oq];
                        fma2(accp[2 * oq    ][0], wv.x, I0);
                        fma2(accp[2 * oq    ][1], wv.x, I1);
                        fma2(accp[2 * oq    ][2], wv.x, I2);
                        fma2(accp[2 * oq    ][3], wv.x, I3);
                        fma2(accp[2 * oq + 1][0], wv.y, I0);
                        fma2(accp[2 * oq + 1][1], wv.y, I1);
                        fma2(accp[2 * oq + 1][2], wv.y, I2);
                        fma2(accp[2 * oq + 1][3], wv.y, I3);
                    }
                }
            }
        }
    }

    const int oy = oy0 + ly;
    const int ox = ox0 + lx;
    const int lane = tid & 31, wrp = tid >> 5;

    #pragma unroll
    for (int p = 0; p < OP; p++) {
        float2 v0 = unpk(accp[p][0]);
        float2 v1 = unpk(accp[p][1]);
        float2 v2 = unpk(accp[p][2]);
        float2 v3 = unpk(accp[p][3]);
        int co0 = g * COG + 2 * p;
        int co1 = co0 + 1;
        if (co0 < coutTotal) {
            float bv = BIAS ? bias[co0] : 0.f;
            float* op = out + ((size_t)b * coutTotal + co0) * HWP;
            op[oy * W64 + ox]           = v0.x + bv;
            op[oy * W64 + ox + 1]       = v1.x + bv;
            op[(oy + 1) * W64 + ox]     = v2.x + bv;
            op[(oy + 1) * W64 + ox + 1] = v3.x + bv;
        }
        if (co1 < coutTotal) {
            float bv = BIAS ? bias[co1] : 0.f;
            float* op = out + ((size_t)b * coutTotal + co1) * HWP;
            op[oy * W64 + ox]           = v0.y + bv;
            op[oy * W64 + ox + 1]       = v1.y + bv;
            op[(oy + 1) * W64 + ox]     = v2.y + bv;
            op[(oy + 1) * W64 + ox + 1] = v3.y + bv;
        }
        if (STATS) {
            float ls0 = v0.x + v1.x + v2.x + v3.x;
            float lq0 = fmaf(v0.x, v0.x, fmaf(v1.x, v1.x, fmaf(v2.x, v2.x, v3.x * v3.x)));
            float ls1 = v0.y + v1.y + v2.y + v3.y;
            float lq1 = fmaf(v0.y, v0.y, fmaf(v1.y, v1.y, fmaf(v2.y, v2.y, v3.y * v3.y)));
            ls0 = warp_sum(ls0); lq0 = warp_sum(lq0);
            ls1 = warp_sum(ls1); lq1 = warp_sum(lq1);
            if (lane == 0) {
                s_red[wrp][2 * p][0] = ls0; s_red[wrp][2 * p][1] = lq0;
                s_red[wrp][2 * p + 1][0] = ls1; s_red[wrp][2 * p + 1][1] = lq1;
            }
        }
    }
    if (STATS) {
        __syncthreads();
        if (tid < COG) {
            float A = 0.f, Q = 0.f;
            #pragma unroll
            for (int w8 = 0; w8 < 8; w8++) { A += s_red[w8][tid][0]; Q += s_red[w8][tid][1]; }
            int co = g * COG + tid;
            if (co < coutTotal) { atomicAdd(&s1[co], A); atomicAdd(&s2[co], Q); }
        }
    }
}

// ---------------- 1x1 conv, 64 -> 16, fused BN1+ReLU on load, stats epilogue ----------------
__global__ void __launch_bounds__(256)
conv1x1_kernel(const float* __restrict__ in, const float* __restrict__ w,
               const float* __restrict__ abn, const float* __restrict__ bbn,
               float* __restrict__ out, float* s1, float* s2)
{
    __shared__ float s_w[64][16];
    __shared__ float s_a[64], s_b[64];
    __shared__ float s_red[8][16][2];
    const int tid = threadIdx.x;
    for (int i = tid; i < 1024; i += 256) {
        int co = i / 64, ci = i % 64;
        s_w[ci][co] = w[co * 64 + ci];
    }
    for (int i = tid; i < 64; i += 256) { s_a[i] = abn[i]; s_b[i] = bbn[i]; }
    __syncthreads();

    const int b = blockIdx.y;
    const int p = blockIdx.x * 256 + tid;
    const float* inb = in + (size_t)b * 64 * HWP + p;
    float acc[16];
    #pragma unroll
    for (int co = 0; co < 16; co++) acc[co] = 0.f;

    #pragma unroll 4
    for (int ci = 0; ci < 64; ci++) {
        float v = inb[(size_t)ci * HWP];
        v = fmaxf(fmaf(v, s_a[ci], s_b[ci]), 0.f);
        #pragma unroll
        for (int co = 0; co < 16; co++) acc[co] = fmaf(v, s_w[ci][co], acc[co]);
    }
    float* ob = out + (size_t)b * 16 * HWP + p;
    const int lane = tid & 31, wrp = tid >> 5;
    #pragma unroll
    for (int co = 0; co < 16; co++) {
        ob[(size_t)co * HWP] = acc[co];
        float ls = warp_sum(acc[co]);
        float lq = warp_sum(acc[co] * acc[co]);
        if (lane == 0) { s_red[wrp][co][0] = ls; s_red[wrp][co][1] = lq; }
    }
    __syncthreads();
    if (tid < 16) {
        float A = 0.f, Q = 0.f;
        #pragma unroll
        for (int w8 = 0; w8 < 8; w8++) { A += s_red[w8][tid][0]; Q += s_red[w8][tid][1]; }
        atomicAdd(&s1[tid], A); atomicAdd(&s2[tid], Q);
    }
}

// ---------------- BN scale/shift from stats ----------------
__global__ void bnparam_kernel(const float* s1, const float* s2,
                               const float* g, const float* be,
                               float* a, float* b, int C)
{
    int c = threadIdx.x;
    if (c < C) {
        const float invN = 1.0f / (float)(NB * HWP);
        float m   = s1[c] * invN;
        float var = s2[c] * invN - m * m;
        float sc  = g[c] * rsqrtf(var + 1e-5f);
        a[c] = sc;
        b[c] = be[c] - m * sc;
    }
}

// ---------------- in-place BN + ReLU (float4) ----------------
__global__ void bnapply4_kernel(float4* x, const float* __restrict__ a,
                                const float* __restrict__ b, int cmask, int total4)
{
    int i = blockIdx.x * blockDim.x + threadIdx.x;
    if (i < total4) {
        int c = (i >> 10) & cmask;
        float4 v = x[i];
        float sa = a[c], sb = b[c];
        v.x = fmaxf(fmaf(v.x, sa, sb), 0.f);
        v.y = fmaxf(fmaf(v.y, sa, sb), 0.f);
        v.z = fmaxf(fmaf(v.z, sa, sb), 0.f);
        v.w = fmaxf(fmaf(v.w, sa, sb), 0.f);
        x[i] = v;
    }
}

// ---------------- BN + residual + ReLU -> output (float4) ----------------
__global__ void resid4_kernel(const float4* __restrict__ y, const float4* __restrict__ x,
                              const float* __restrict__ a, const float* __restrict__ b,
                              float4* __restrict__ out, int total4)
{
    int i = blockIdx.x * blockDim.x + threadIdx.x;
    if (i < total4) {
        int c = (i >> 10) & 63;
        float4 v = y[i], r = x[i], o;
        float sa = a[c], sb = b[c];
        o.x = fmaxf(fmaf(v.x, sa, sb) + r.x, 0.f);
        o.y = fmaxf(fmaf(v.y, sa, sb) + r.y, 0.f);
        o.z = fmaxf(fmaf(v.z, sa, sb) + r.z, 0.f);
        o.w = fmaxf(fmaf(v.w, sa, sb) + r.w, 0.f);
        out[i] = o;
    }
}

// ---------------- deformable 3x3 conv, 16 -> 16, pad=1, f32x2 + stats ----------------
__global__ void __launch_bounds__(256)
deform_kernel(const float* __restrict__ x, const float* __restrict__ off,
              const float* __restrict__ w, float* __restrict__ out,
              float* s1, float* s2)
{
    __shared__ __align__(16) float s_w[9][16][16];
    __shared__ float s_red[8][16][2];
    const int tid = threadIdx.x;
    for (int i = tid; i < 2304; i += 256) {
        int o = i / 144;
        int r = i % 144;
        int c = r / 9;
        int k = r % 9;
        s_w[k][c][o] = w[i];
    }
    __syncthreads();

    const int b  = blockIdx.z;
    const int ox = blockIdx.x * 16 + (tid & 15);
    const int oy = blockIdx.y * 16 + (tid >> 4);

    const float* xb   = x   + (size_t)b * 16 * HWP;
    const float* offb = off + (size_t)b * 18 * HWP + oy * W64 + ox;

    u64 accp[8];
    #pragma unroll
    for (int p = 0; p < 8; p++) accp[p] = 0ull;

    #pragma unroll 1
    for (int k = 0; k < 9; k++) {
        int ky = k / 3, kx = k % 3;
        float py = (float)(oy + ky) + offb[(size_t)k * HWP];
        float px = (float)(ox + kx) + offb[(size_t)(9 + k) * HWP];
        py = fminf(fmaxf(py, 0.f), 65.f);
        px = fminf(fmaxf(px, 0.f), 65.f);
        float fy = floorf(py), fx = floorf(px);
        int y0 = (int)fy, x0 = (int)fx;
        int y1 = min(y0 + 1, 65), x1 = min(x0 + 1, 65);
        float wy = py - fy, wx = px - fx;
        float w00 = (1.f - wy) * (1.f - wx);
        float w01 = (1.f - wy) * wx;
        float w10 = wy * (1.f - wx);
        float w11 = wy * wx;
        bool vy0 = (y0 >= 1 && y0 <= 64);
        bool vy1 = (y1 >= 1 && y1 <= 64);
        bool vx0 = (x0 >= 1 && x0 <= 64);
        bool vx1 = (x1 >= 1 && x1 <= 64);
        int iy0 = (y0 - 1) * W64, iy1 = (y1 - 1) * W64;
        int ix0 = x0 - 1, ix1 = x1 - 1;

        #pragma unroll 1
        for (int c = 0; c < 16; c++) {
            const float* xc = xb + (size_t)c * HWP;
            float v00 = (vy0 && vx0) ? __ldg(xc + iy0 + ix0) : 0.f;
            float v01 = (vy0 && vx1) ? __ldg(xc + iy0 + ix1) : 0.f;
            float v10 = (vy1 && vx0) ? __ldg(xc + iy1 + ix0) : 0.f;
            float v11 = (vy1 && vx1) ? __ldg(xc + iy1 + ix1) : 0.f;
            float s = fmaf(v00, w00, fmaf(v01, w01, fmaf(v10, w10, v11 * w11)));
            u64 S = dup2(s);
            ulonglong2 wa = *(const ulonglong2*)&s_w[k][c][0];
            ulonglong2 wb = *(const ulonglong2*)&s_w[k][c][4];
            ulonglong2 wc = *(const ulonglong2*)&s_w[k][c][8];
            ulonglong2 wd = *(const ulonglong2*)&s_w[k][c][12];
            fma2(accp[0], wa.x, S); fma2(accp[1], wa.y, S);
            fma2(accp[2], wb.x, S); fma2(accp[3], wb.y, S);
            fma2(accp[4], wc.x, S); fma2(accp[5], wc.y, S);
            fma2(accp[6], wd.x, S); fma2(accp[7], wd.y, S);
        }
    }

    float* ob = out + (size_t)b * 16 * HWP + oy * W64 + ox;
    const int lane = tid & 31, wrp = tid >> 5;
    #pragma unroll
    for (int p = 0; p < 8; p++) {
        float2 v = unpk(accp[p]);
        ob[(size_t)(2 * p) * HWP]     = v.x;
        ob[(size_t)(2 * p + 1) * HWP] = v.y;
        float ls0 = warp_sum(v.x);
        float lq0 = warp_sum(v.x * v.x);
        float ls1 = warp_sum(v.y);
        float lq1 = warp_sum(v.y * v.y);
        if (lane == 0) {
            s_red[wrp][2 * p][0] = ls0;     s_red[wrp][2 * p][1] = lq0;
            s_red[wrp][2 * p + 1][0] = ls1; s_red[wrp][2 * p + 1][1] = lq1;
        }
    }
    __syncthreads();
    if (tid < 16) {
        float A = 0.f, Q = 0.f;
        #pragma unroll
        for (int w8 = 0; w8 < 8; w8++) { A += s_red[w8][tid][0]; Q += s_red[w8][tid][1]; }
        atomicAdd(&s1[tid], A); atomicAdd(&s2[tid], Q);
    }
}

// ---------------- launch ----------------
extern "C" void kernel_launch(void* const* d_in, const int* in_sizes, int n_in,
                              void* d_out, int out_size)
{
    const float* x    = (const float*)d_in[0];
    const float* c1w  = (const float*)d_in[1];
    const float* bn1g = (const float*)d_in[2];
    const float* bn1b = (const float*)d_in[3];
    const float* c2w  = (const float*)d_in[4];
    const float* bn2g = (const float*)d_in[5];
    const float* bn2b = (const float*)d_in[6];
    const float* offw = (const float*)d_in[7];
    const float* offb = (const float*)d_in[8];
    const float* c3w  = (const float*)d_in[9];
    const float* bn3g = (const float*)d_in[10];
    const float* bn3b = (const float*)d_in[11];
    const float* c4w  = (const float*)d_in[12];
    const float* bn4g = (const float*)d_in[13];
    const float* bn4b = (const float*)d_in[14];
    float* out = (float*)d_out;

    float *buf1, *buf2, *offs, *buf3, *buf4, *stats, *bnp;
    cudaGetSymbolAddress((void**)&buf1,  g_buf1);
    cudaGetSymbolAddress((void**)&buf2,  g_buf2);
    cudaGetSymbolAddress((void**)&offs,  g_offs);
    cudaGetSymbolAddress((void**)&buf3,  g_buf3);
    cudaGetSymbolAddress((void**)&buf4,  g_buf4);
    cudaGetSymbolAddress((void**)&stats, g_stats);
    cudaGetSymbolAddress((void**)&bnp,   g_bnp);

    static bool attr_done = false;
    if (!attr_done) {
        cudaFuncSetAttribute(conv3x3_mma<64, false>,
                             cudaFuncAttributeMaxDynamicSharedMemorySize, MMA_SMEM_BYTES);
        cudaFuncSetAttribute(conv3x3_mma<16, true>,
                             cudaFuncAttributeMaxDynamicSharedMemorySize, MMA_SMEM_BYTES);
        attr_done = true;
    }

    const int TOT64 = NB * 64 * HWP;   // 16,777,216
    const int TOT16 = NB * 16 * HWP;   //  4,194,304

    zero_stats_kernel<<<1, 320>>>(stats);

    // stage 1: conv1 (64->64, tf32 mma) with fused stats epilogue
    conv3x3_mma<64, false><<<dim3(8, NB), 256, MMA_SMEM_BYTES>>>(
        x, c1w, nullptr, nullptr, buf1, stats + 0, stats + 64);
    bnparam_kernel<<<1, 64>>>(stats + 0, stats + 64, bn1g, bn1b, bnp + 0, bnp + 64, 64);

    // stage 2: conv2 1x1 (BN1+ReLU fused on load) with fused stats epilogue
    conv1x1_kernel<<<dim3(16, NB), 256>>>(buf1, c2w, bnp + 0, bnp + 64,
                                          buf2, stats + 128, stats + 144);
    bnparam_kernel<<<1, 16>>>(stats + 128, stats + 144, bn2g, bn2b, bnp + 128, bnp + 144, 16);
    bnapply4_kernel<<<(TOT16 / 4 + 255) / 256, 256>>>((float4*)buf2, bnp + 128, bnp + 144,
                                                      15, TOT16 / 4);

    // stage 3: offset conv (FFMA2, 16->18+bias), deform (+stats)
    conv3x3_kernel<16, 20, true, false, false><<<dim3(2, 2, NB), 256>>>(
        buf2, offw, offb, nullptr, nullptr, offs, nullptr, nullptr, 1, 18);
    deform_kernel<<<dim3(4, 4, NB), 256>>>(buf2, offs, c3w, buf3, stats + 160, stats + 176);
    bnparam_kernel<<<1, 16>>>(stats + 160, stats + 176, bn3g, bn3b, bnp + 160, bnp + 176, 16);

    // stage 4: conv4 (16->64, tf32 mma, BN3+ReLU fused on in-bounds staging) + stats
    conv3x3_mma<16, true><<<dim3(8, NB), 256, MMA_SMEM_BYTES>>>(
        buf3, c4w, bnp + 160, bnp + 176, buf4, stats + 192, stats + 256);
    bnparam_kernel<<<1, 64>>>(stats + 192, stats + 256, bn4g, bn4b, bnp + 192, bnp + 256, 64);

    // residual + BN4 + ReLU
    resid4_kernel<<<(TOT64 / 4 + 255) / 256, 256>>>((const float4*)buf4, (const float4*)x,
                                                    bnp + 192, bnp + 256, (float4*)out, TOT64 / 4);
}

// round 12
// speedup vs baseline: 2.4287x; 1.1304x over previous
#include <cuda_runtime.h>
#include <math.h>
#include <stdint.h>

// Problem constants
#define NB   64     // batch
#define H64  64
#define W64  64
#define HWP  4096   // 64*64

typedef unsigned long long u64;

// ---------------- scratch (device globals; no allocation allowed) ----------------
__device__ float g_buf1[(size_t)NB * 64 * HWP];   // conv1 out (raw)
__device__ float g_buf2[(size_t)NB * 16 * HWP];   // conv2 out (raw, then BN+ReLU in place)
__device__ float g_offs[(size_t)NB * 18 * HWP];   // offset conv out
__device__ float g_buf3[(size_t)NB * 16 * HWP];   // deform conv out (raw)
__device__ float g_buf4[(size_t)NB * 64 * HWP];   // conv4 out (raw)
__device__ float g_stats[320];                    // per-stage sum / sumsq
__device__ float g_bnp[320];                      // per-stage scale / shift

// ---------------- helpers ----------------
__device__ __forceinline__ float warp_sum(float v) {
    #pragma unroll
    for (int s = 16; s > 0; s >>= 1) v += __shfl_xor_sync(0xffffffffu, v, s);
    return v;
}

// packed fp32x2 (FFMA2) — used by offconv / deform
__device__ __forceinline__ u64 dup2(float v) {
    u64 r; asm("mov.b64 %0, {%1, %1};" : "=l"(r) : "f"(v)); return r;
}
__device__ __forceinline__ void fma2(u64& d, u64 a, u64 b) {
    asm("fma.rn.f32x2 %0, %1, %2, %0;" : "+l"(d) : "l"(a), "l"(b));
}
__device__ __forceinline__ float2 unpk(u64 v) {
    float2 f; asm("mov.b64 {%0, %1}, %2;" : "=f"(f.x), "=f"(f.y) : "l"(v)); return f;
}

// tf32 round-to-nearest conversion
__device__ __forceinline__ uint32_t to_tf32(float f) {
    uint32_t r; asm("cvt.rna.tf32.f32 %0, %1;" : "=r"(r) : "f"(f)); return r;
}

// m16n8k8 tf32 MMA, fp32 accumulate
__device__ __forceinline__ void mma_tf32(float* d,
    uint32_t a0, uint32_t a1, uint32_t a2, uint32_t a3,
    uint32_t b0, uint32_t b1)
{
    asm volatile(
        "mma.sync.aligned.m16n8k8.row.col.f32.tf32.tf32.f32 "
        "{%0,%1,%2,%3}, {%4,%5,%6,%7}, {%8,%9}, {%0,%1,%2,%3};"
        : "+f"(d[0]), "+f"(d[1]), "+f"(d[2]), "+f"(d[3])
        : "r"(a0), "r"(a1), "r"(a2), "r"(a3), "r"(b0), "r"(b1));
}

__global__ void zero_stats_kernel(float* s) {
    s[threadIdx.x] = 0.0f;   // 320 threads
}

// ======================================================================
// 3x3 conv (pad=1) as 9 per-tap tf32 GEMMs, COUT=64.
// CTA: 512 threads / 16 warps; tile = 8 image rows x full width (64).
// Warp (row = wid>>1, half = wid&1) owns 32 pixels of its row:
//   2 m-tiles of 16 pixels x 8 n-tiles of 8 cout -> 64 fp32 acc/thread.
// K = CIN*9, ci-chunks of 16 (x 9 taps x 2 sub-chunks of 8).
// Optional fused BN+ReLU on input staging (in-bounds cells ONLY).
// Per-channel sum/sumsq epilogue always on.
// ======================================================================
#define MMA_SMEM_U32  (16 * 664 + 9 * 16 * 72)
#define MMA_SMEM_BYTES (MMA_SMEM_U32 * 4)

template<int CIN, bool INBN>
__global__ void __launch_bounds__(512, 1)
conv3x3_mma(const float* __restrict__ in, const float* __restrict__ w,
            const float* __restrict__ abn, const float* __restrict__ bbn,
            float* __restrict__ out, float* s1, float* s2)
{
    constexpr int NCH = CIN / 16;             // ci chunks of 16
    extern __shared__ uint32_t dynsm[];
    uint32_t* s_in = dynsm;                   // [ci][yy*66+xx], plane stride 664
    uint32_t* s_w  = dynsm + 16 * 664;        // [tap][ci][72]
    __shared__ float s_bn[2][CIN];
    __shared__ float s_red[16][64][2];

    const int b   = blockIdx.y;
    const int y0  = blockIdx.x * 8;
    const int tid = threadIdx.x;              // 0..511
    const int wid = tid >> 5;                 // 0..15
    const int lane = tid & 31;
    const int g   = lane >> 2;                // 0..7
    const int tig = lane & 3;                 // 0..3
    const int row = wid >> 1;                 // 0..7 image row within tile
    const int hx  = (wid & 1) * 32;           // x half offset

    const float* inb = in + (size_t)b * CIN * HWP;

    if (INBN) {
        for (int i = tid; i < CIN; i += 512) { s_bn[0][i] = abn[i]; s_bn[1][i] = bbn[i]; }
    }

    float acc[2][8][4];                       // [m-tile][n-tile][frag]
    #pragma unroll
    for (int mt = 0; mt < 2; mt++)
        #pragma unroll
        for (int nt = 0; nt < 8; nt++)
            #pragma unroll
            for (int r = 0; r < 4; r++) acc[mt][nt][r] = 0.f;

    for (int cc = 0; cc < NCH; cc++) {
        __syncthreads();
        // ---- stage input chunk: 16 ci x 10 rows x 66 cols, tf32-RNA ----
        for (int i = tid; i < 16 * 660; i += 512) {
            int ci = i / 660, r = i % 660, yy = r / 66, xx = r % 66;
            int gy = y0 + yy - 1, gx = xx - 1;
            float v = 0.f;
            if (gy >= 0 && gy < H64 && gx >= 0 && gx < W64) {
                v = inb[(size_t)(cc * 16 + ci) * HWP + gy * W64 + gx];
                if (INBN) v = fmaxf(fmaf(v, s_bn[0][cc * 16 + ci], s_bn[1][cc * 16 + ci]), 0.f);
            }
            s_in[ci * 664 + yy * 66 + xx] = to_tf32(v);
        }
        // ---- stage weights: w[(co*CIN + ci)*9 + tap] -> s_w[tap][ci][co] ----
        for (int i = tid; i < 9 * 16 * 64; i += 512) {
            int co = i & 63, ci = (i >> 6) & 15, tap = i >> 10;
            float v = w[((size_t)co * CIN + cc * 16 + ci) * 9 + tap];
            s_w[tap * (16 * 72) + ci * 72 + co] = to_tf32(v);
        }
        __syncthreads();

        #pragma unroll 1
        for (int tap = 0; tap < 9; tap++) {
            const int ky = tap / 3, kx = tap % 3;
            #pragma unroll
            for (int ks = 0; ks < 2; ks++) {
                // B fragments: k = ks*8 + tig (+4), n = nt*8 + g
                const uint32_t* wp = s_w + tap * (16 * 72) + (ks * 8 + tig) * 72;
                uint32_t bf0[8], bf1[8];
                #pragma unroll
                for (int nt = 0; nt < 8; nt++) {
                    bf0[nt] = wp[nt * 8 + g];
                    bf1[nt] = wp[4 * 72 + nt * 8 + g];
                }
                // A fragments: pixel row = y0+row, x = hx + mt*16 + g (+8); ci = ks*8 + tig (+4)
                const uint32_t* ip = s_in + (ks * 8 + tig) * 664 + (row + ky) * 66 + kx + hx;
                #pragma unroll
                for (int mt = 0; mt < 2; mt++) {
                    uint32_t a0 = ip[mt * 16 + g];
                    uint32_t a1 = ip[mt * 16 + g + 8];
                    uint32_t a2 = ip[4 * 664 + mt * 16 + g];
                    uint32_t a3 = ip[4 * 664 + mt * 16 + g + 8];
                    #pragma unroll
                    for (int nt = 0; nt < 8; nt++)
                        mma_tf32(acc[mt][nt], a0, a1, a2, a3, bf0[nt], bf1[nt]);
                }
            }
        }
    }

    // ---- epilogue: store + per-channel stats ----
    const int y = y0 + row;
    float* ob = out + (size_t)b * 64 * HWP + y * W64 + hx;
    #pragma unroll
    for (int nt = 0; nt < 8; nt++) {
        const int co = nt * 8 + 2 * tig;
        float se = 0.f, qe = 0.f, so = 0.f, qo = 0.f;
        #pragma unroll
        for (int mt = 0; mt < 2; mt++) {
            const int x = mt * 16 + g;
            float c0 = acc[mt][nt][0], c1 = acc[mt][nt][1];
            float c2 = acc[mt][nt][2], c3 = acc[mt][nt][3];
            ob[(size_t)co * HWP + x]           = c0;   // px x,   col 2tig
            ob[(size_t)(co + 1) * HWP + x]     = c1;   // px x,   col 2tig+1
            ob[(size_t)co * HWP + x + 8]       = c2;   // px x+8, col 2tig
            ob[(size_t)(co + 1) * HWP + x + 8] = c3;
            se += c0 + c2; qe += fmaf(c0, c0, c2 * c2);
            so += c1 + c3; qo += fmaf(c1, c1, c3 * c3);
        }
        // reduce over g (lane bits 2..4)
        #pragma unroll
        for (int m = 4; m < 32; m <<= 1) {
            se += __shfl_xor_sync(0xffffffffu, se, m);
            qe += __shfl_xor_sync(0xffffffffu, qe, m);
            so += __shfl_xor_sync(0xffffffffu, so, m);
            qo += __shfl_xor_sync(0xffffffffu, qo, m);
        }
        if (g == 0) {
            s_red[wid][co][0] = se;     s_red[wid][co][1] = qe;
            s_red[wid][co + 1][0] = so; s_red[wid][co + 1][1] = qo;
        }
    }
    __syncthreads();
    if (tid < 64) {
        float A = 0.f, Q = 0.f;
        #pragma unroll
        for (int w16 = 0; w16 < 16; w16++) { A += s_red[w16][tid][0]; Q += s_red[w16][tid][1]; }
        atomicAdd(&s1[tid], A); atomicAdd(&s2[tid], Q);
    }
}

// ---------------- direct 3x3 conv (FFMA2) — used for the offset conv ----------------
template<int CIN, int COG, bool BIAS, bool INBN, bool STATS>
__global__ void __launch_bounds__(256)
conv3x3_kernel(const float* __restrict__ in, const float* __restrict__ w,
               const float* __restrict__ bias,
               const float* __restrict__ abn, const float* __restrict__ bbn,
               float* __restrict__ out, float* s1, float* s2,
               int nGrp, int coutTotal)
{
    constexpr int TX = 32, TY = 32, CCH = 8;
    constexpr int OP = COG / 2;
    __shared__ __align__(16) float s_in[CCH][TY + 2][TX + 4];
    __shared__ __align__(16) float s_w[CCH][9][COG];
    __shared__ float s_a[CIN], s_b[CIN];
    __shared__ float s_red[8][COG][2];

    const int bz = blockIdx.z;
    const int b = bz / nGrp;
    const int g = bz % nGrp;
    const int ox0 = blockIdx.x * TX;
    const int oy0 = blockIdx.y * TY;
    const int tid = threadIdx.x;
    const int lx = (tid & 15) * 2;
    const int ly = (tid >> 4) * 2;

    const float* inb = in + (size_t)b * CIN * HWP;

    if (INBN) {
        for (int i = tid; i < CIN; i += 256) { s_a[i] = abn[i]; s_b[i] = bbn[i]; }
    }

    u64 accp[OP][4];
    #pragma unroll
    for (int p = 0; p < OP; p++) {
        accp[p][0] = 0ull; accp[p][1] = 0ull; accp[p][2] = 0ull; accp[p][3] = 0ull;
    }

    for (int c0 = 0; c0 < CIN; c0 += CCH) {
        __syncthreads();
        for (int i = tid; i < CCH * 34 * 34; i += 256) {
            int ci = i / (34 * 34);
            int r  = i % (34 * 34);
            int yy = r / 34;
            int xx = r % 34;
            int gy = oy0 + yy - 1;
            int gx = ox0 + xx - 1;
            float v = 0.f;
            if (gy >= 0 && gy < H64 && gx >= 0 && gx < W64) {
                v = inb[(size_t)(c0 + ci) * HWP + gy * W64 + gx];
                if (INBN) v = fmaxf(fmaf(v, s_a[c0 + ci], s_b[c0 + ci]), 0.f);
            }
            s_in[ci][yy][xx] = v;
        }
        for (int i = tid; i < CCH * 9 * COG; i += 256) {
            int ci  = i / (9 * COG);
            int r   = i % (9 * COG);
            int k   = r / COG;
            int lco = r % COG;
            int co  = g * COG + lco;
            s_w[ci][k][lco] = (co < coutTotal)
                ? w[((size_t)co * CIN + (c0 + ci)) * 9 + k] : 0.f;
        }
        __syncthreads();

        #pragma unroll 1
        for (int ci = 0; ci < CCH; ci++) {
            float r4[4][4];
            #pragma unroll
            for (int y = 0; y < 4; y++) {
                float2 t0 = *(const float2*)&s_in[ci][ly + y][lx];
                float2 t1 = *(const float2*)&s_in[ci][ly + y][lx + 2];
                r4[y][0] = t0.x; r4[y][1] = t0.y; r4[y][2] = t1.x; r4[y][3] = t1.y;
            }
            #pragma unroll
            for (int ky = 0; ky < 3; ky++) {
                #pragma unroll
                for (int kx = 0; kx < 3; kx++) {
                    const int k = ky * 3 + kx;
                    u64 I0 = dup2(r4[ky    ][kx    ]);
                    u64 I1 = dup2(r4[ky    ][kx + 1]);
                    u64 I2 = dup2(r4[ky + 1][kx    ]);
                    u64 I3 = dup2(r4[ky + 1][kx + 1]);
                    #pragma unroll
                    for (int oq = 0; oq < COG / 4; oq++) {
                        ulonglong2 wv = *(const ulonglong2*)&s_w[ci][k][4 * oq];
                        fma2(accp[2 * oq    ][0], wv.x, I0);
                        fma2(accp[2 * oq    ][1], wv.x, I1);
                        fma2(accp[2 * oq    ][2], wv.x, I2);
                        fma2(accp[2 * oq    ][3], wv.x, I3);
                        fma2(accp[2 * oq + 1][0], wv.y, I0);
                        fma2(accp[2 * oq + 1][1], wv.y, I1);
                        fma2(accp[2 * oq + 1][2], wv.y, I2);
                        fma2(accp[2 * oq + 1][3], wv.y, I3);
                    }
                }
            }
        }
    }

    const int oy = oy0 + ly;
    const int ox = ox0 + lx;
    const int lane = tid & 31, wrp = tid >> 5;

    #pragma unroll
    for (int p = 0; p < OP; p++) {
        float2 v0 = unpk(accp[p][0]);
        float2 v1 = unpk(accp[p][1]);
        float2 v2 = unpk(accp[p][2]);
        float2 v3 = unpk(accp[p][3]);
        int co0 = g * COG + 2 * p;
        int co1 = co0 + 1;
        if (co0 < coutTotal) {
            float bv = BIAS ? bias[co0] : 0.f;
            float* op = out + ((size_t)b * coutTotal + co0) * HWP;
            op[oy * W64 + ox]           = v0.x + bv;
            op[oy * W64 + ox + 1]       = v1.x + bv;
            op[(oy + 1) * W64 + ox]     = v2.x + bv;
            op[(oy + 1) * W64 + ox + 1] = v3.x + bv;
        }
        if (co1 < coutTotal) {
            float bv = BIAS ? bias[co1] : 0.f;
            float* op = out + ((size_t)b * coutTotal + co1) * HWP;
            op[oy * W64 + ox]           = v0.y + bv;
            op[oy * W64 + ox + 1]       = v1.y + bv;
            op[(oy + 1) * W64 + ox]     = v2.y + bv;
            op[(oy + 1) * W64 + ox + 1] = v3.y + bv;
        }
        if (STATS) {
            float ls0 = v0.x + v1.x + v2.x + v3.x;
            float lq0 = fmaf(v0.x, v0.x, fmaf(v1.x, v1.x, fmaf(v2.x, v2.x, v3.x * v3.x)));
            float ls1 = v0.y + v1.y + v2.y + v3.y;
            float lq1 = fmaf(v0.y, v0.y, fmaf(v1.y, v1.y, fmaf(v2.y, v2.y, v3.y * v3.y)));
            ls0 = warp_sum(ls0); lq0 = warp_sum(lq0);
            ls1 = warp_sum(ls1); lq1 = warp_sum(lq1);
            if (lane == 0) {
                s_red[wrp][2 * p][0] = ls0; s_red[wrp][2 * p][1] = lq0;
                s_red[wrp][2 * p + 1][0] = ls1; s_red[wrp][2 * p + 1][1] = lq1;
            }
        }
    }
    if (STATS) {
        __syncthreads();
        if (tid < COG) {
            float A = 0.f, Q = 0.f;
            #pragma unroll
            for (int w8 = 0; w8 < 8; w8++) { A += s_red[w8][tid][0]; Q += s_red[w8][tid][1]; }
            int co = g * COG + tid;
            if (co < coutTotal) { atomicAdd(&s1[co], A); atomicAdd(&s2[co], Q); }
        }
    }
}

// ---------------- 1x1 conv, 64 -> 16, float4 pixels, fused BN1+ReLU, stats ----------------
__global__ void __launch_bounds__(256)
conv1x1_kernel(const float4* __restrict__ in4, const float* __restrict__ w,
               const float* __restrict__ abn, const float* __restrict__ bbn,
               float4* __restrict__ out4, float* s1, float* s2)
{
    __shared__ float s_w[64][16];
    __shared__ float s_a[64], s_b[64];
    __shared__ float s_red[8][16][2];
    const int tid = threadIdx.x;
    for (int i = tid; i < 1024; i += 256) {
        int co = i / 64, ci = i % 64;
        s_w[ci][co] = w[co * 64 + ci];
    }
    for (int i = tid; i < 64; i += 256) { s_a[i] = abn[i]; s_b[i] = bbn[i]; }
    __syncthreads();

    const int b  = blockIdx.y;
    const int p4 = blockIdx.x * 256 + tid;   // float4 index within plane (0..1023)
    const float4* inb = in4 + (size_t)b * 64 * 1024 + p4;

    float4 acc[16];
    #pragma unroll
    for (int co = 0; co < 16; co++) acc[co] = make_float4(0.f, 0.f, 0.f, 0.f);

    #pragma unroll 4
    for (int ci = 0; ci < 64; ci++) {
        float4 v = inb[(size_t)ci * 1024];
        float sa = s_a[ci], sb = s_b[ci];
        v.x = fmaxf(fmaf(v.x, sa, sb), 0.f);
        v.y = fmaxf(fmaf(v.y, sa, sb), 0.f);
        v.z = fmaxf(fmaf(v.z, sa, sb), 0.f);
        v.w = fmaxf(fmaf(v.w, sa, sb), 0.f);
        #pragma unroll
        for (int co = 0; co < 16; co++) {
            float wc = s_w[ci][co];
            acc[co].x = fmaf(v.x, wc, acc[co].x);
            acc[co].y = fmaf(v.y, wc, acc[co].y);
            acc[co].z = fmaf(v.z, wc, acc[co].z);
            acc[co].w = fmaf(v.w, wc, acc[co].w);
        }
    }
    float4* ob = out4 + (size_t)b * 16 * 1024 + p4;
    const int lane = tid & 31, wrp = tid >> 5;
    #pragma unroll
    for (int co = 0; co < 16; co++) {
        ob[(size_t)co * 1024] = acc[co];
        float ls = acc[co].x + acc[co].y + acc[co].z + acc[co].w;
        float lq = fmaf(acc[co].x, acc[co].x, fmaf(acc[co].y, acc[co].y,
                   fmaf(acc[co].z, acc[co].z, acc[co].w * acc[co].w)));
        ls = warp_sum(ls); lq = warp_sum(lq);
        if (lane == 0) { s_red[wrp][co][0] = ls; s_red[wrp][co][1] = lq; }
    }
    __syncthreads();
    if (tid < 16) {
        float A = 0.f, Q = 0.f;
        #pragma unroll
        for (int w8 = 0; w8 < 8; w8++) { A += s_red[w8][tid][0]; Q += s_red[w8][tid][1]; }
        atomicAdd(&s1[tid], A); atomicAdd(&s2[tid], Q);
    }
}

// ---------------- BN scale/shift from stats ----------------
__global__ void bnparam_kernel(const float* s1, const float* s2,
                               const float* g, const float* be,
                               float* a, float* b, int C)
{
    int c = threadIdx.x;
    if (c < C) {
        const float invN = 1.0f / (float)(NB * HWP);
        float m   = s1[c] * invN;
        float var = s2[c] * invN - m * m;
        float sc  = g[c] * rsqrtf(var + 1e-5f);
        a[c] = sc;
        b[c] = be[c] - m * sc;
    }
}

// ---------------- in-place BN + ReLU (float4) ----------------
__global__ void bnapply4_kernel(float4* x, const float* __restrict__ a,
                                const float* __restrict__ b, int cmask, int total4)
{
    int i = blockIdx.x * blockDim.x + threadIdx.x;
    if (i < total4) {
        int c = (i >> 10) & cmask;
        float4 v = x[i];
        float sa = a[c], sb = b[c];
        v.x = fmaxf(fmaf(v.x, sa, sb), 0.f);
        v.y = fmaxf(fmaf(v.y, sa, sb), 0.f);
        v.z = fmaxf(fmaf(v.z, sa, sb), 0.f);
        v.w = fmaxf(fmaf(v.w, sa, sb), 0.f);
        x[i] = v;
    }
}

// ---------------- BN + residual + ReLU -> output (float4) ----------------
__global__ void resid4_kernel(const float4* __restrict__ y, const float4* __restrict__ x,
                              const float* __restrict__ a, const float* __restrict__ b,
                              float4* __restrict__ out, int total4)
{
    int i = blockIdx.x * blockDim.x + threadIdx.x;
    if (i < total4) {
        int c = (i >> 10) & 63;
        float4 v = y[i], r = x[i], o;
        float sa = a[c], sb = b[c];
        o.x = fmaxf(fmaf(v.x, sa, sb) + r.x, 0.f);
        o.y = fmaxf(fmaf(v.y, sa, sb) + r.y, 0.f);
        o.z = fmaxf(fmaf(v.z, sa, sb) + r.z, 0.f);
        o.w = fmaxf(fmaf(v.w, sa, sb) + r.w, 0.f);
        out[i] = o;
    }
}

// ---------------- deformable 3x3 conv, 16 -> 16, pad=1, f32x2 + stats ----------------
__global__ void __launch_bounds__(256)
deform_kernel(const float* __restrict__ x, const float* __restrict__ off,
              const float* __restrict__ w, float* __restrict__ out,
              float* s1, float* s2)
{
    __shared__ __align__(16) float s_w[9][16][16];
    __shared__ float s_red[8][16][2];
    const int tid = threadIdx.x;
    for (int i = tid; i < 2304; i += 256) {
        int o = i / 144;
        int r = i % 144;
        int c = r / 9;
        int k = r % 9;
        s_w[k][c][o] = w[i];
    }
    __syncthreads();

    const int b  = blockIdx.z;
    const int ox = blockIdx.x * 16 + (tid & 15);
    const int oy = blockIdx.y * 16 + (tid >> 4);

    const float* xb   = x   + (size_t)b * 16 * HWP;
    const float* offb = off + (size_t)b * 18 * HWP + oy * W64 + ox;

    u64 accp[8];
    #pragma unroll
    for (int p = 0; p < 8; p++) accp[p] = 0ull;

    #pragma unroll 1
    for (int k = 0; k < 9; k++) {
        int ky = k / 3, kx = k % 3;
        float py = (float)(oy + ky) + offb[(size_t)k * HWP];
        float px = (float)(ox + kx) + offb[(size_t)(9 + k) * HWP];
        py = fminf(fmaxf(py, 0.f), 65.f);
        px = fminf(fmaxf(px, 0.f), 65.f);
        float fy = floorf(py), fx = floorf(px);
        int y0 = (int)fy, x0 = (int)fx;
        int y1 = min(y0 + 1, 65), x1 = min(x0 + 1, 65);
        float wy = py - fy, wx = px - fx;
        float w00 = (1.f - wy) * (1.f - wx);
        float w01 = (1.f - wy) * wx;
        float w10 = wy * (1.f - wx);
        float w11 = wy * wx;
        bool vy0 = (y0 >= 1 && y0 <= 64);
        bool vy1 = (y1 >= 1 && y1 <= 64);
        bool vx0 = (x0 >= 1 && x0 <= 64);
        bool vx1 = (x1 >= 1 && x1 <= 64);
        int iy0 = (y0 - 1) * W64, iy1 = (y1 - 1) * W64;
        int ix0 = x0 - 1, ix1 = x1 - 1;

        #pragma unroll 1
        for (int c = 0; c < 16; c++) {
            const float* xc = xb + (size_t)c * HWP;
            float v00 = (vy0 && vx0) ? __ldg(xc + iy0 + ix0) : 0.f;
            float v01 = (vy0 && vx1) ? __ldg(xc + iy0 + ix1) : 0.f;
            float v10 = (vy1 && vx0) ? __ldg(xc + iy1 + ix0) : 0.f;
            float v11 = (vy1 && vx1) ? __ldg(xc + iy1 + ix1) : 0.f;
            float s = fmaf(v00, w00, fmaf(v01, w01, fmaf(v10, w10, v11 * w11)));
            u64 S = dup2(s);
            ulonglong2 wa = *(const ulonglong2*)&s_w[k][c][0];
            ulonglong2 wb = *(const ulonglong2*)&s_w[k][c][4];
            ulonglong2 wc = *(const ulonglong2*)&s_w[k][c][8];
            ulonglong2 wd = *(const ulonglong2*)&s_w[k][c][12];
            fma2(accp[0], wa.x, S); fma2(accp[1], wa.y, S);
            fma2(accp[2], wb.x, S); fma2(accp[3], wb.y, S);
            fma2(accp[4], wc.x, S); fma2(accp[5], wc.y, S);
            fma2(accp[6], wd.x, S); fma2(accp[7], wd.y, S);
        }
    }

    float* ob = out + (size_t)b * 16 * HWP + oy * W64 + ox;
    const int lane = tid & 31, wrp = tid >> 5;
    #pragma unroll
    for (int p = 0; p < 8; p++) {
        float2 v = unpk(accp[p]);
        ob[(size_t)(2 * p) * HWP]     = v.x;
        ob[(size_t)(2 * p + 1) * HWP] = v.y;
        float ls0 = warp_sum(v.x);
        float lq0 = warp_sum(v.x * v.x);
        float ls1 = warp_sum(v.y);
        float lq1 = warp_sum(v.y * v.y);
        if (lane == 0) {
            s_red[wrp][2 * p][0] = ls0;     s_red[wrp][2 * p][1] = lq0;
            s_red[wrp][2 * p + 1][0] = ls1; s_red[wrp][2 * p + 1][1] = lq1;
        }
    }
    __syncthreads();
    if (tid < 16) {
        float A = 0.f, Q = 0.f;
        #pragma unroll
        for (int w8 = 0; w8 < 8; w8++) { A += s_red[w8][tid][0]; Q += s_red[w8][tid][1]; }
        atomicAdd(&s1[tid], A); atomicAdd(&s2[tid], Q);
    }
}

// ---------------- launch ----------------
extern "C" void kernel_launch(void* const* d_in, const int* in_sizes, int n_in,
                              void* d_out, int out_size)
{
    const float* x    = (const float*)d_in[0];
    const float* c1w  = (const float*)d_in[1];
    const float* bn1g = (const float*)d_in[2];
    const float* bn1b = (const float*)d_in[3];
    const float* c2w  = (const float*)d_in[4];
    const float* bn2g = (const float*)d_in[5];
    const float* bn2b = (const float*)d_in[6];
    const float* offw = (const float*)d_in[7];
    const float* offb = (const float*)d_in[8];
    const float* c3w  = (const float*)d_in[9];
    const float* bn3g = (const float*)d_in[10];
    const float* bn3b = (const float*)d_in[11];
    const float* c4w  = (const float*)d_in[12];
    const float* bn4g = (const float*)d_in[13];
    const float* bn4b = (const float*)d_in[14];
    float* out = (float*)d_out;

    float *buf1, *buf2, *offs, *buf3, *buf4, *stats, *bnp;
    cudaGetSymbolAddress((void**)&buf1,  g_buf1);
    cudaGetSymbolAddress((void**)&buf2,  g_buf2);
    cudaGetSymbolAddress((void**)&offs,  g_offs);
    cudaGetSymbolAddress((void**)&buf3,  g_buf3);
    cudaGetSymbolAddress((void**)&buf4,  g_buf4);
    cudaGetSymbolAddress((void**)&stats, g_stats);
    cudaGetSymbolAddress((void**)&bnp,   g_bnp);

    static bool attr_done = false;
    if (!attr_done) {
        cudaFuncSetAttribute(conv3x3_mma<64, false>,
                             cudaFuncAttributeMaxDynamicSharedMemorySize, MMA_SMEM_BYTES);
        cudaFuncSetAttribute(conv3x3_mma<16, true>,
                             cudaFuncAttributeMaxDynamicSharedMemorySize, MMA_SMEM_BYTES);
        attr_done = true;
    }

    const int TOT64 = NB * 64 * HWP;   // 16,777,216
    const int TOT16 = NB * 16 * HWP;   //  4,194,304

    zero_stats_kernel<<<1, 320>>>(stats);

    // stage 1: conv1 (64->64, tf32 mma, 512 thr) with fused stats epilogue
    conv3x3_mma<64, false><<<dim3(8, NB), 512, MMA_SMEM_BYTES>>>(
        x, c1w, nullptr, nullptr, buf1, stats + 0, stats + 64);
    bnparam_kernel<<<1, 64>>>(stats + 0, stats + 64, bn1g, bn1b, bnp + 0, bnp + 64, 64);

    // stage 2: conv2 1x1 (float4 pixels, BN1+ReLU fused on load) with fused stats epilogue
    conv1x1_kernel<<<dim3(4, NB), 256>>>((const float4*)buf1, c2w, bnp + 0, bnp + 64,
                                         (float4*)buf2, stats + 128, stats + 144);
    bnparam_kernel<<<1, 16>>>(stats + 128, stats + 144, bn2g, bn2b, bnp + 128, bnp + 144, 16);
    bnapply4_kernel<<<(TOT16 / 4 + 255) / 256, 256>>>((float4*)buf2, bnp + 128, bnp + 144,
                                                      15, TOT16 / 4);

    // stage 3: offset conv (FFMA2, 16->18+bias), deform (+stats)
    conv3x3_kernel<16, 20, true, false, false><<<dim3(2, 2, NB), 256>>>(
        buf2, offw, offb, nullptr, nullptr, offs, nullptr, nullptr, 1, 18);
    deform_kernel<<<dim3(4, 4, NB), 256>>>(buf2, offs, c3w, buf3, stats + 160, stats + 176);
    bnparam_kernel<<<1, 16>>>(stats + 160, stats + 176, bn3g, bn3b, bnp + 160, bnp + 176, 16);

    // stage 4: conv4 (16->64, tf32 mma 512 thr, BN3+ReLU fused on in-bounds staging) + stats
    conv3x3_mma<16, true><<<dim3(8, NB), 512, MMA_SMEM_BYTES>>>(
        buf3, c4w, bnp + 160, bnp + 176, buf4, stats + 192, stats + 256);
    bnparam_kernel<<<1, 64>>>(stats + 192, stats + 256, bn4g, bn4b, bnp + 192, bnp + 256, 64);

    // residual + BN4 + ReLU
    resid4_kernel<<<(TOT64 / 4 + 255) / 256, 256>>>((const float4*)buf4, (const float4*)x,
                                                    bnp + 192, bnp + 256, (float4*)out, TOT64 / 4);
}